// round 2
// baseline (speedup 1.0000x reference)
#include <cuda_runtime.h>

// ---------------- problem constants (fixed shapes) ----------------
#define B_     2
#define NPART  512
#define BN     1024          // B_*NPART
#define KDIM   8
#define GBINS  48            // R_BINS(3) * T_BINS(16)
#define TWO_PI 6.283185307179586f
#define INV_2PI 0.15915494309189535f

// ---------------- device scratch (static, no allocation) ----------------
__device__ float    g_p1[BN * 2];
__device__ float    g_regC[BN * 128];         // lifted fluid feats (lift_c0), C=16,K=8
__device__ float    g_regD[BN * 128];         // lifted fluid feats (lift_d0)
__device__ float4   g_w4[BN * NPART];         // 4 bin weights per pair (incl. wb, normalized)
__device__ unsigned g_g4[BN * NPART];         // 4 packed bin indices per pair
__device__ float    g_F[BN * GBINS * 128];    // stage-1 output, max CK=128
__device__ float    g_out[BN * 128];          // current layer output (max 16 ch * 8)
__device__ float    g_act[BN * 128];          // mag_act(output)
__device__ float    g_Wbig[6144 * 128];       // expanded conv kernel [kk][om]
__device__ float    g_WdT[128 * 128];         // expanded dense kernel [cn][om]
__device__ float    g_oc[BN * 24];            // last-layer conv out (reg space)
__device__ float    g_od[BN * 24];            // last-layer dense out (reg space)

// ---------------- prep: p1, v1, lifted features ----------------
__global__ void prep_kernel(const float* __restrict__ p0_enc,
                            const float* __restrict__ v0_enc,
                            const float* __restrict__ p0,
                            const float* __restrict__ v0,
                            const float* __restrict__ a,
                            const float* __restrict__ lc,
                            const float* __restrict__ ld) {
    int bi = blockIdx.x;
    int tid = threadIdx.x;          // 128 threads: c*8 + m
    int c = tid >> 3, m = tid & 7;

    float v0x = v0[bi * 2 + 0], v0y = v0[bi * 2 + 1];
    float ax = a[bi * 2 + 0], ay = a[bi * 2 + 1];
    float v1x = v0x + ax, v1y = v0y + ay;                  // DT = 1
    float p1x = p0[bi * 2 + 0] + 0.5f * (v0x + v1x);
    float p1y = p0[bi * 2 + 1] + 0.5f * (v0y + v1y);
    if (tid == 0) { g_p1[bi * 2 + 0] = p1x; g_p1[bi * 2 + 1] = p1y; }

    float x, y;
    if (c == 0)      { x = v1x; y = v1y; }
    else if (c == 1) { x = p1x; y = p1y; }
    else if (c < 9)  { int t = c - 2; x = v0_enc[(bi * 7 + t) * 2 + 0]; y = v0_enc[(bi * 7 + t) * 2 + 1]; }
    else             { int t = c - 9; x = p0_enc[(bi * 7 + t) * 2 + 0]; y = p0_enc[(bi * 7 + t) * 2 + 1]; }

    float th = (float)m * 0.78539816339744831f;
    float cs = cosf(th), sn = sinf(th);
    float lc0 = lc[0], lc1 = lc[1], ld0 = ld[0], ld1 = ld[1];
    // basis M[m] = ab0*(cos,sin) + ab1*(-sin,cos); reg = x*M0 + y*M1
    g_regC[bi * 128 + tid] = x * (lc0 * cs - lc1 * sn) + y * (lc0 * sn + lc1 * cs);
    g_regD[bi * 128 + tid] = x * (ld0 * cs - ld1 * sn) + y * (ld0 * sn + ld1 * cs);
}

// ---------------- pair geometry: normalized 4-bin weights per pair ----------------
__global__ void geom_kernel(const float* __restrict__ mask) {
    __shared__ float sx[NPART], sy[NPART], sm[NPART], sw[NPART];
    __shared__ float red[256];
    int bi = blockIdx.x;
    int b = bi >> 9, i = bi & 511;
    int tid = threadIdx.x;          // 256

    for (int j = tid; j < NPART; j += 256) {
        sx[j] = g_p1[(b * NPART + j) * 2 + 0];
        sy[j] = g_p1[(b * NPART + j) * 2 + 1];
        sm[j] = mask[b * NPART + j];
    }
    __syncthreads();
    float xi = sx[i], yi = sy[i];

    float part = 0.f;
    for (int j = tid; j < NPART; j += 256) {
        float rx = sx[j] - xi, ry = sy[j] - yi;
        float d = sqrtf(rx * rx + ry * ry + 1e-12f) * 0.025f;   // /RADIUS
        float u = fmaxf(1.f - d * d, 0.f);
        float w = u * u * u * sm[j];
        sw[j] = w;
        part += w;
    }
    red[tid] = part;
    __syncthreads();
    for (int s = 128; s > 0; s >>= 1) { if (tid < s) red[tid] += red[tid + s]; __syncthreads(); }
    float inv = 1.f / (red[0] + 1e-6f);

    for (int j = tid; j < NPART; j += 256) {
        float wb = sw[j] * inv;
        float rx = sx[j] - xi, ry = sy[j] - yi;
        float d = sqrtf(rx * rx + ry * ry + 1e-12f) * 0.025f;
        float rc = fminf(fmaxf(d * 3.f - 0.5f, 0.f), 2.f);
        float r0 = floorf(rc);
        float wr = rc - r0;
        int r0i = (int)r0;
        int r1i = min(r0i + 1, 2);
        float axv = (j == i) ? 1.f : rx;
        float ayv = (j == i) ? 0.f : ry;
        float ang = atan2f(ayv, axv);
        ang = ang - TWO_PI * floorf(ang * INV_2PI);              // mod 2pi
        float tc = ang * (16.f * INV_2PI);
        float t0 = floorf(tc);
        float wt = tc - t0;
        int t0i = ((int)t0) & 15;
        int t1i = (t0i + 1) & 15;
        int g0 = r0i * 16 + t0i, g1 = r0i * 16 + t1i;
        int g2 = r1i * 16 + t0i, g3 = r1i * 16 + t1i;
        g_w4[(size_t)bi * NPART + j] = make_float4((1.f - wr) * (1.f - wt) * wb,
                                                   (1.f - wr) * wt * wb,
                                                   wr * (1.f - wt) * wb,
                                                   wr * wt * wb);
        g_g4[(size_t)bi * NPART + j] = (unsigned)g0 | ((unsigned)g1 << 8) |
                                       ((unsigned)g2 << 16) | ((unsigned)g3 << 24);
    }
}

// ---------------- per-layer kernel expansions ----------------
// Wbig[kk][om], kk = (g*C + c)*8 + n, om = o*8 + m
// value = Wc[o, c, (n-m)%8, r, (t-2m)%16],  g = r*16 + t
__global__ void expand_kernel(const float* __restrict__ Wc, int C, int O) {
    int OK = O * 8;
    int total = GBINS * C * 8 * OK;
    int idx = blockIdx.x * blockDim.x + threadIdx.x;
    if (idx >= total) return;
    int om = idx % OK;
    int kk = idx / OK;
    int n = kk & 7;
    int c = (kk >> 3) % C;
    int g = (kk >> 3) / C;
    int r = g >> 4, t = g & 15;
    int o = om >> 3, m = om & 7;
    int nn = (n - m) & 7;
    int tt = (t - 2 * m) & 15;
    g_Wbig[idx] = Wc[(((o * C + c) * 8 + nn) * 3 + r) * 16 + tt];
}

// WdT[cn][om] = Wd[o, c, (m-n)%8]
__global__ void expandd_kernel(const float* __restrict__ Wd, int C, int O) {
    int OK = O * 8, CK = C * 8;
    int total = CK * OK;
    int idx = blockIdx.x * blockDim.x + threadIdx.x;
    if (idx >= total) return;
    int om = idx % OK;
    int cn = idx / OK;
    int o = om >> 3, m = om & 7, c = cn >> 3, n = cn & 7;
    g_WdT[idx] = Wd[(o * C + c) * 8 + ((m - n) & 7)];
}

// ---------------- mag_act ----------------
__global__ void magact_kernel() {
    int bi = blockIdx.x;
    int tid = threadIdx.x;                    // CK threads (64 or 128)
    float v = g_out[bi * blockDim.x + tid];
    float sq = v * v;
    sq += __shfl_xor_sync(0xffffffffu, sq, 1);
    sq += __shfl_xor_sync(0xffffffffu, sq, 2);
    sq += __shfl_xor_sync(0xffffffffu, sq, 4);
    float mags = sq + 1e-6f;
    g_act[bi * blockDim.x + tid] = v / mags * fmaxf(mags - 0.2f, 0.f);
}

// ---------------- stage 1: sparse bin scatter F[i,g,c,n] ----------------
__global__ void stage1_kernel(int srcflag, int CK) {
    extern __shared__ float Fs[];             // GBINS * CK floats
    int bi = blockIdx.x;
    int b = bi >> 9;
    int tid = threadIdx.x;                    // CK threads; each owns a feature lane
    const float* __restrict__ feats = srcflag ? g_act : g_regC;

    for (int k = tid; k < GBINS * CK; k += CK) Fs[k] = 0.f;
    __syncthreads();

    const float4*   wp = g_w4 + (size_t)bi * NPART;
    const unsigned* gp = g_g4 + (size_t)bi * NPART;
    const float*    frow = feats + (size_t)b * NPART * CK;

    for (int j = 0; j < NPART; ++j) {
        float4 w = wp[j];
        if ((w.x + w.y + w.z + w.w) == 0.f) continue;   // weights are non-negative
        unsigned g = gp[j];
        float f = frow[j * CK + tid];
        Fs[(g & 255u) * CK + tid]         += w.x * f;
        Fs[((g >> 8) & 255u) * CK + tid]  += w.y * f;
        Fs[((g >> 16) & 255u) * CK + tid] += w.z * f;
        Fs[(g >> 24) * CK + tid]          += w.w * f;
    }
    // each thread owns its own column; no sync needed
    float* out = g_F + (size_t)bi * GBINS * CK;
    for (int k = tid; k < GBINS * CK; k += CK) out[k] = Fs[k];
}

// ---------------- stage 2: GEMM over kk + dense path + epilogue ----------------
// modes: 0 = concat (layer0), 1 = sum, 2 = sum + residual, 3 = last (write oc/od)
template <int OK, int NS, int ROWS>
__global__ void stage2_kernel(int CK, int KD, int mode) {
    const int TM = 8;
    __shared__ float4 Fs4[TM * 16];           // TM rows x 64 floats
    float* Fs = (float*)Fs4;
    int tid = threadIdx.x;
    int grp = tid / OK;                       // 0..NS-1
    int om = tid % OK;
    int i0 = blockIdx.x * TM;

    float acc[ROWS];
#pragma unroll
    for (int r = 0; r < ROWS; ++r) acc[r] = 0.f;

    int nch = KD >> 6;
    for (int ch = 0; ch < nch; ++ch) {
        int k0 = ch << 6;
        __syncthreads();
        for (int x = tid; x < TM * 64; x += OK * NS)
            Fs[x] = g_F[(size_t)(i0 + (x >> 6)) * KD + k0 + (x & 63)];
        __syncthreads();
        const float* wbp = g_Wbig + (size_t)k0 * OK + om;
#pragma unroll 4
        for (int cc = 0; cc < 64; cc += 4) {
            float w0 = wbp[(cc + 0) * OK];
            float w1 = wbp[(cc + 1) * OK];
            float w2 = wbp[(cc + 2) * OK];
            float w3 = wbp[(cc + 3) * OK];
#pragma unroll
            for (int r = 0; r < ROWS; ++r) {
                int ti = grp + r * NS;
                if (ti < TM) {
                    float4 f = Fs4[ti * 16 + (cc >> 2)];
                    acc[r] = fmaf(w0, f.x, acc[r]);
                    acc[r] = fmaf(w1, f.y, acc[r]);
                    acc[r] = fmaf(w2, f.z, acc[r]);
                    acc[r] = fmaf(w3, f.w, acc[r]);
                }
            }
        }
    }

    const float* __restrict__ densein = (mode == 0) ? g_regD : g_act;
#pragma unroll
    for (int r = 0; r < ROWS; ++r) {
        int ti = grp + r * NS;
        if (ti >= TM) continue;
        int bi = i0 + ti;
        const float* x = densein + (size_t)bi * CK;
        float od = 0.f;
        for (int cn = 0; cn < CK; ++cn) od = fmaf(x[cn], g_WdT[cn * OK + om], od);
        float oc = acc[r];
        if (mode == 0) {                       // concat: conv ch 0..3, dense ch 4..7
            g_out[bi * 64 + om] = oc;
            g_out[bi * 64 + 32 + om] = od;
        } else if (mode == 3) {
            g_oc[bi * 24 + om] = oc;
            g_od[bi * 24 + om] = od;
        } else {
            float v = oc + od;
            if (mode == 2) v += g_out[bi * OK + om];
            g_out[bi * OK + om] = v;
        }
    }
}

// ---------------- final: projection + position correction ----------------
__global__ void final_kernel(const float* __restrict__ p0,
                             const float* __restrict__ pc,
                             const float* __restrict__ pd,
                             float* __restrict__ outp) {
    int bi = blockIdx.x * blockDim.x + threadIdx.x;
    if (bi >= BN) return;
    float res[3][2] = {{0.f, 0.f}, {0.f, 0.f}, {0.f, 0.f}};
    float c0 = pc[0], c1 = pc[1], d0 = pd[0], d1 = pd[1];
#pragma unroll
    for (int m = 0; m < 8; ++m) {
        float th = (float)m * 0.78539816339744831f;
        float cs = cosf(th), sn = sinf(th);
        float Mc0 = c0 * cs - c1 * sn, Mc1 = c0 * sn + c1 * cs;
        float Md0 = d0 * cs - d1 * sn, Md1 = d0 * sn + d1 * cs;
#pragma unroll
        for (int ch = 0; ch < 3; ++ch) {
            float vc = g_oc[bi * 24 + ch * 8 + m];
            float vd = g_od[bi * 24 + ch * 8 + m];
            res[ch][0] += vc * Mc0 + vd * Md0;
            res[ch][1] += vc * Mc1 + vd * Md1;
        }
    }
    const float CORR = 1.0f / 128.0f;
    float pcx = g_p1[bi * 2 + 0] + CORR * res[0][0];
    float pcy = g_p1[bi * 2 + 1] + CORR * res[0][1];
    outp[bi * 2 + 0] = pcx;
    outp[bi * 2 + 1] = pcy;
    outp[BN * 2 + bi * 2 + 0] = pcx - p0[bi * 2 + 0];   // DT = 1
    outp[BN * 2 + bi * 2 + 1] = pcy - p0[bi * 2 + 1];
    outp[BN * 4 + bi * 4 + 0] = CORR * res[1][0];
    outp[BN * 4 + bi * 4 + 1] = CORR * res[1][1];
    outp[BN * 4 + bi * 4 + 2] = CORR * res[2][0];
    outp[BN * 4 + bi * 4 + 3] = CORR * res[2][1];
}

// ---------------- launch ----------------
extern "C" void kernel_launch(void* const* d_in, const int* in_sizes, int n_in,
                              void* d_out, int out_size) {
    const float* p0_enc  = (const float*)d_in[0];
    const float* v0_enc  = (const float*)d_in[1];
    const float* p0      = (const float*)d_in[2];
    const float* v0      = (const float*)d_in[3];
    const float* a       = (const float*)d_in[4];
    const float* mask    = (const float*)d_in[5];
    const float* lift_c0 = (const float*)d_in[6];
    const float* Wc0     = (const float*)d_in[7];
    const float* lift_d0 = (const float*)d_in[8];
    const float* Wd0     = (const float*)d_in[9];
    const float* Wc1     = (const float*)d_in[10];
    const float* Wd1     = (const float*)d_in[11];
    const float* Wc2     = (const float*)d_in[12];
    const float* Wd2     = (const float*)d_in[13];
    const float* Wc3     = (const float*)d_in[14];
    const float* Wd3     = (const float*)d_in[15];
    const float* Wc4     = (const float*)d_in[16];
    const float* proj_c4 = (const float*)d_in[17];
    const float* Wd4     = (const float*)d_in[18];
    const float* proj_d4 = (const float*)d_in[19];

    prep_kernel<<<BN, 128>>>(p0_enc, v0_enc, p0, v0, a, lift_c0, lift_d0);
    geom_kernel<<<BN, 256>>>(mask);

    const float* WcA[5] = {Wc0, Wc1, Wc2, Wc3, Wc4};
    const float* WdA[5] = {Wd0, Wd1, Wd2, Wd3, Wd4};
    const int Cs[5]    = {16, 8, 8, 16, 8};
    const int Os[5]    = {4, 8, 16, 8, 3};
    const int modes[5] = {0, 2, 1, 1, 3};

    for (int l = 0; l < 5; ++l) {
        int C = Cs[l], O = Os[l];
        int CK = C * 8, OK = O * 8, KD = GBINS * CK;
        int tot = KD * OK;
        expand_kernel<<<(tot + 255) / 256, 256>>>(WcA[l], C, O);
        int totd = CK * OK;
        expandd_kernel<<<(totd + 255) / 256, 256>>>(WdA[l], C, O);
        if (l > 0) magact_kernel<<<BN, CK>>>();
        stage1_kernel<<<BN, CK, GBINS * CK * (int)sizeof(float)>>>(l > 0 ? 1 : 0, CK);
        switch (l) {
            case 0: stage2_kernel<32, 4, 2><<<BN / 8, 128>>>(CK, KD, modes[l]); break;
            case 1: stage2_kernel<64, 2, 4><<<BN / 8, 128>>>(CK, KD, modes[l]); break;
            case 2: stage2_kernel<128, 1, 8><<<BN / 8, 128>>>(CK, KD, modes[l]); break;
            case 3: stage2_kernel<64, 2, 4><<<BN / 8, 128>>>(CK, KD, modes[l]); break;
            case 4: stage2_kernel<24, 5, 2><<<BN / 8, 120>>>(CK, KD, modes[l]); break;
        }
    }

    final_kernel<<<4, 256>>>(p0, proj_c4, proj_d4, (float*)d_out);
}

// round 4
// speedup vs baseline: 1.0362x; 1.0362x over previous
#include <cuda_runtime.h>

#define B_     2
#define NPART  512
#define BN     1024
#define GBINS  48
#define TWO_PI 6.283185307179586f
#define INV_2PI 0.15915494309189535f

// ---------------- static device scratch ----------------
__device__ float    g_p1[BN * 2];
__device__ float    g_regC[BN * 128];
__device__ float    g_regD[BN * 128];
__device__ float4   g_w4c[BN * NPART];        // compacted 4-bin weights
__device__ unsigned g_gc[BN * NPART];         // compacted packed bin indices
__device__ int      g_jc[BN * NPART];         // compacted neighbor j
__device__ int      g_cnt[BN];
__device__ float    g_F[BN * GBINS * 128];
__device__ float    g_out[BN * 128];
__device__ float    g_actA[BN * 128];         // activation ping
__device__ float    g_actB[BN * 128];         // activation pong
__device__ float    g_Wbig[1253376];
__device__ float    g_WdT[26112];
__device__ float    g_oc[BN * 24];
__device__ float    g_od[BN * 24];

__constant__ int c_wOff[6] = {0, 196608, 393216, 786432, 1179648, 1253376};
__constant__ int c_dOff[6] = {0, 4096, 8192, 16384, 24576, 26112};

// ---------------- lift: rho1 -> regular rep ----------------
__global__ void lift_kernel(const float* __restrict__ p0_enc,
                            const float* __restrict__ v0_enc,
                            const float* __restrict__ p0,
                            const float* __restrict__ v0,
                            const float* __restrict__ a,
                            const float* __restrict__ lc,
                            const float* __restrict__ ld) {
    int bi = blockIdx.x;
    int tid = threadIdx.x;          // 128: c*8+m
    int c = tid >> 3, m = tid & 7;

    float v0x = v0[bi * 2 + 0], v0y = v0[bi * 2 + 1];
    float ax = a[bi * 2 + 0], ay = a[bi * 2 + 1];
    float v1x = v0x + ax, v1y = v0y + ay;
    float p1x = p0[bi * 2 + 0] + 0.5f * (v0x + v1x);
    float p1y = p0[bi * 2 + 1] + 0.5f * (v0y + v1y);

    float x, y;
    if (c == 0)      { x = v1x; y = v1y; }
    else if (c == 1) { x = p1x; y = p1y; }
    else if (c < 9)  { int t = c - 2; x = v0_enc[(bi * 7 + t) * 2 + 0]; y = v0_enc[(bi * 7 + t) * 2 + 1]; }
    else             { int t = c - 9; x = p0_enc[(bi * 7 + t) * 2 + 0]; y = p0_enc[(bi * 7 + t) * 2 + 1]; }

    float th = (float)m * 0.78539816339744831f;
    float cs = cosf(th), sn = sinf(th);
    float lc0 = lc[0], lc1 = lc[1], ld0 = ld[0], ld1 = ld[1];
    g_regC[bi * 128 + tid] = x * (lc0 * cs - lc1 * sn) + y * (lc0 * sn + lc1 * cs);
    g_regD[bi * 128 + tid] = x * (ld0 * cs - ld1 * sn) + y * (ld0 * sn + ld1 * cs);
}

// ---------------- geometry + deterministic compaction ----------------
__global__ void __launch_bounds__(256) geom_kernel(const float* __restrict__ mask,
                                                   const float* __restrict__ p0,
                                                   const float* __restrict__ v0,
                                                   const float* __restrict__ a) {
    __shared__ float sx[NPART], sy[NPART], smk[NPART], sw[NPART];
    __shared__ float red[256];
    __shared__ int warpcnt[8];
    __shared__ int s_base;
    int bi = blockIdx.x;
    int b = bi >> 9, i = bi & 511;
    int tid = threadIdx.x;

    for (int j = tid; j < NPART; j += 256) {
        int gj = b * NPART + j;
        float vx = v0[gj * 2], vy = v0[gj * 2 + 1];
        sx[j] = p0[gj * 2 + 0] + vx + 0.5f * a[gj * 2 + 0];
        sy[j] = p0[gj * 2 + 1] + vy + 0.5f * a[gj * 2 + 1];
        smk[j] = mask[gj];
    }
    __syncthreads();
    if (tid == 0) { g_p1[bi * 2] = sx[i]; g_p1[bi * 2 + 1] = sy[i]; s_base = 0; }
    float xi = sx[i], yi = sy[i];

    float part = 0.f;
    for (int j = tid; j < NPART; j += 256) {
        float rx = sx[j] - xi, ry = sy[j] - yi;
        float d2 = (rx * rx + ry * ry + 1e-12f) * (0.025f * 0.025f);
        float u = fmaxf(1.f - d2, 0.f);
        float w = u * u * u * smk[j];
        sw[j] = w;
        part += w;
    }
    red[tid] = part;
    __syncthreads();
    for (int s = 128; s > 0; s >>= 1) { if (tid < s) red[tid] += red[tid + s]; __syncthreads(); }
    float inv = 1.f / (red[0] + 1e-6f);
    __syncthreads();

    for (int c = 0; c < 2; ++c) {
        int j = c * 256 + tid;
        float w = sw[j];
        bool pred = (w > 0.f);
        unsigned bal = __ballot_sync(0xffffffffu, pred);
        int lane = tid & 31, warp = tid >> 5;
        if (lane == 0) warpcnt[warp] = __popc(bal);
        __syncthreads();
        int base = s_base;
        for (int ww = 0; ww < warp; ++ww) base += warpcnt[ww];
        int pos = base + __popc(bal & ((1u << lane) - 1u));
        if (pred) {
            float rx = sx[j] - xi, ry = sy[j] - yi;
            float d = sqrtf(rx * rx + ry * ry + 1e-12f) * 0.025f;
            float wb = w * inv;
            float rc = fminf(fmaxf(d * 3.f - 0.5f, 0.f), 2.f);
            float r0 = floorf(rc);
            float wr = rc - r0;
            int r0i = (int)r0;
            int r1i = min(r0i + 1, 2);
            float axv = (j == i) ? 1.f : rx;
            float ayv = (j == i) ? 0.f : ry;
            float ang = atan2f(ayv, axv);
            ang = ang - TWO_PI * floorf(ang * INV_2PI);
            float tc = ang * (16.f * INV_2PI);
            float t0 = floorf(tc);
            float wt = tc - t0;
            int t0i = ((int)t0) & 15;
            int t1i = (t0i + 1) & 15;
            int g0 = r0i * 16 + t0i, g1 = r0i * 16 + t1i;
            int g2 = r1i * 16 + t0i, g3 = r1i * 16 + t1i;
            size_t o = (size_t)bi * NPART + pos;
            g_w4c[o] = make_float4((1.f - wr) * (1.f - wt) * wb,
                                   (1.f - wr) * wt * wb,
                                   wr * (1.f - wt) * wb,
                                   wr * wt * wb);
            g_gc[o] = (unsigned)g0 | ((unsigned)g1 << 8) |
                      ((unsigned)g2 << 16) | ((unsigned)g3 << 24);
            g_jc[o] = j;
        }
        __syncthreads();
        if (tid == 0) {
            int t = 0;
            for (int ww = 0; ww < 8; ++ww) t += warpcnt[ww];
            s_base += t;
        }
        __syncthreads();
    }
    if (tid == 0) g_cnt[bi] = s_base;
}

// ---------------- expand all weights (5 layers, conv + dense) ----------------
__global__ void expand_all(const float* __restrict__ Wc0, const float* __restrict__ Wc1,
                           const float* __restrict__ Wc2, const float* __restrict__ Wc3,
                           const float* __restrict__ Wc4,
                           const float* __restrict__ Wd0, const float* __restrict__ Wd1,
                           const float* __restrict__ Wd2, const float* __restrict__ Wd3,
                           const float* __restrict__ Wd4) {
    const int Cs[5] = {16, 8, 8, 16, 8};
    const int Os[5] = {4, 8, 16, 8, 3};
    int idx = blockIdx.x * 256 + threadIdx.x;
    if (idx < 1253376) {
        int l = 0;
        while (idx >= c_wOff[l + 1]) ++l;
        int loc = idx - c_wOff[l];
        const float* Wc = (l == 0) ? Wc0 : (l == 1) ? Wc1 : (l == 2) ? Wc2 : (l == 3) ? Wc3 : Wc4;
        int C = Cs[l], OK = Os[l] * 8;
        int om = loc % OK;
        int kk = loc / OK;
        int n = kk & 7;
        int c = (kk >> 3) % C;
        int g = (kk >> 3) / C;
        int r = g >> 4, t = g & 15;
        int o = om >> 3, m = om & 7;
        g_Wbig[idx] = Wc[(((o * C + c) * 8 + ((n - m) & 7)) * 3 + r) * 16 + ((t - 2 * m) & 15)];
    } else if (idx < 1253376 + 26112) {
        int id2 = idx - 1253376;
        int l = 0;
        while (id2 >= c_dOff[l + 1]) ++l;
        int loc = id2 - c_dOff[l];
        const float* Wd = (l == 0) ? Wd0 : (l == 1) ? Wd1 : (l == 2) ? Wd2 : (l == 3) ? Wd3 : Wd4;
        int C = Cs[l], OK = Os[l] * 8;
        int om = loc % OK;
        int cn = loc / OK;
        int o = om >> 3, m = om & 7, c = cn >> 3, n = cn & 7;
        g_WdT[id2] = Wd[(o * C + c) * 8 + ((m - n) & 7)];
    }
}

// ---------------- stage 1: compacted sparse bin scatter, NG-way j split ----------------
// srcsel: 0 = g_regC, 1 = g_actA, 2 = g_actB
template <int CK, int NG>
__global__ void __launch_bounds__(256) stage1_kernel(int srcsel) {
    extern __shared__ float Fs[];
    int bi = blockIdx.x;
    int b = bi >> 9;
    int tid = threadIdx.x;
    int grp = tid / CK, lane = tid % CK;
    const float* __restrict__ feats = (srcsel == 0) ? g_regC : (srcsel == 1) ? g_actA : g_actB;

    for (int x = tid; x < NG * GBINS * CK; x += 256) Fs[x] = 0.f;
    __syncthreads();

    int cnt = g_cnt[bi];
    int k0 = grp * cnt / NG, k1 = (grp + 1) * cnt / NG;
    const float4*   wp = g_w4c + (size_t)bi * NPART;
    const unsigned* gp = g_gc + (size_t)bi * NPART;
    const int*      jp = g_jc + (size_t)bi * NPART;
    const float*    fb = feats + (size_t)b * NPART * CK;
    float* F = Fs + grp * GBINS * CK;

#pragma unroll 2
    for (int k = k0; k < k1; ++k) {
        float4 w = wp[k];
        unsigned g = gp[k];
        float f = fb[jp[k] * CK + lane];
        F[(g & 255u) * CK + lane]         += w.x * f;
        F[((g >> 8) & 255u) * CK + lane]  += w.y * f;
        F[((g >> 16) & 255u) * CK + lane] += w.z * f;
        F[(g >> 24) * CK + lane]          += w.w * f;
    }
    __syncthreads();

    float* out = g_F + (size_t)bi * GBINS * CK;
    for (int x = tid; x < GBINS * CK; x += 256) {
        float s = Fs[x];
#pragma unroll
        for (int c2 = 1; c2 < NG; ++c2) s += Fs[c2 * GBINS * CK + x];
        out[x] = s;
    }
}

// ---------------- stage 2: GEMM + dense + epilogue + fused mag_act ----------------
// modes: 0 = concat (layer0), 1 = sum, 2 = sum + residual, 3 = last (write oc/od)
// actin_sel: 0 = g_regD (layer0 dense in), 1 = g_actA, 2 = g_actB
// actout_sel: 1 = g_actA, 2 = g_actB (ignored for mode 3)
template <int OK, int NS, int ROWS>
__global__ void stage2_kernel(int CK, int KD, int mode, int wOff, int dOff,
                              int actin_sel, int actout_sel) {
    const int TM = 8;
    __shared__ float4 Fs4[TM * 16];
    float* Fs = (float*)Fs4;
    int tid = threadIdx.x;
    int grp = tid / OK;
    int om = tid % OK;
    int i0 = blockIdx.x * TM;

    float acc[ROWS];
#pragma unroll
    for (int r = 0; r < ROWS; ++r) acc[r] = 0.f;

    const float* Wbig = g_Wbig + wOff;
    int nch = KD >> 6;
    for (int ch = 0; ch < nch; ++ch) {
        int k0 = ch << 6;
        __syncthreads();
        for (int x = tid; x < TM * 64; x += OK * NS)
            Fs[x] = g_F[(size_t)(i0 + (x >> 6)) * KD + k0 + (x & 63)];
        __syncthreads();
        const float* wbp = Wbig + (size_t)k0 * OK + om;
#pragma unroll 4
        for (int cc = 0; cc < 64; cc += 4) {
            float w0 = wbp[(cc + 0) * OK];
            float w1 = wbp[(cc + 1) * OK];
            float w2 = wbp[(cc + 2) * OK];
            float w3 = wbp[(cc + 3) * OK];
#pragma unroll
            for (int r = 0; r < ROWS; ++r) {
                int ti = grp + r * NS;
                if (ti < TM) {
                    float4 f = Fs4[ti * 16 + (cc >> 2)];
                    acc[r] = fmaf(w0, f.x, acc[r]);
                    acc[r] = fmaf(w1, f.y, acc[r]);
                    acc[r] = fmaf(w2, f.z, acc[r]);
                    acc[r] = fmaf(w3, f.w, acc[r]);
                }
            }
        }
    }

    const float* __restrict__ densein = (actin_sel == 0) ? g_regD :
                                        (actin_sel == 1) ? g_actA : g_actB;
    float* __restrict__ actout = (actout_sel == 1) ? g_actA : g_actB;
    const float* WdT = g_WdT + dOff;
#pragma unroll
    for (int r = 0; r < ROWS; ++r) {
        int ti = grp + r * NS;
        if (ti >= TM) continue;
        int bi = i0 + ti;
        const float* x = densein + (size_t)bi * CK;
        float od = 0.f;
        for (int cn = 0; cn < CK; ++cn) od = fmaf(x[cn], WdT[cn * OK + om], od);
        float oc = acc[r];
        if (mode == 0) {
            g_out[bi * 64 + om] = oc;
            g_out[bi * 64 + 32 + om] = od;
            float sc = oc * oc;
            sc += __shfl_xor_sync(0xffffffffu, sc, 1);
            sc += __shfl_xor_sync(0xffffffffu, sc, 2);
            sc += __shfl_xor_sync(0xffffffffu, sc, 4);
            float mc = sc + 1e-6f;
            actout[bi * 64 + om] = oc / mc * fmaxf(mc - 0.2f, 0.f);
            float sd = od * od;
            sd += __shfl_xor_sync(0xffffffffu, sd, 1);
            sd += __shfl_xor_sync(0xffffffffu, sd, 2);
            sd += __shfl_xor_sync(0xffffffffu, sd, 4);
            float md = sd + 1e-6f;
            actout[bi * 64 + 32 + om] = od / md * fmaxf(md - 0.2f, 0.f);
        } else if (mode == 3) {
            g_oc[bi * 24 + om] = oc;
            g_od[bi * 24 + om] = od;
        } else {
            float v = oc + od;
            if (mode == 2) v += g_out[bi * OK + om];
            g_out[bi * OK + om] = v;
            float sq = v * v;
            sq += __shfl_xor_sync(0xffffffffu, sq, 1);
            sq += __shfl_xor_sync(0xffffffffu, sq, 2);
            sq += __shfl_xor_sync(0xffffffffu, sq, 4);
            float mg = sq + 1e-6f;
            actout[bi * OK + om] = v / mg * fmaxf(mg - 0.2f, 0.f);
        }
    }
}

// ---------------- final projection + correction ----------------
__global__ void final_kernel(const float* __restrict__ p0,
                             const float* __restrict__ pc,
                             const float* __restrict__ pd,
                             float* __restrict__ outp) {
    int bi = blockIdx.x * blockDim.x + threadIdx.x;
    if (bi >= BN) return;
    float res[3][2] = {{0.f, 0.f}, {0.f, 0.f}, {0.f, 0.f}};
    float c0 = pc[0], c1 = pc[1], d0 = pd[0], d1 = pd[1];
#pragma unroll
    for (int m = 0; m < 8; ++m) {
        float th = (float)m * 0.78539816339744831f;
        float cs = cosf(th), sn = sinf(th);
        float Mc0 = c0 * cs - c1 * sn, Mc1 = c0 * sn + c1 * cs;
        float Md0 = d0 * cs - d1 * sn, Md1 = d0 * sn + d1 * cs;
#pragma unroll
        for (int ch = 0; ch < 3; ++ch) {
            float vc = g_oc[bi * 24 + ch * 8 + m];
            float vd = g_od[bi * 24 + ch * 8 + m];
            res[ch][0] += vc * Mc0 + vd * Md0;
            res[ch][1] += vc * Mc1 + vd * Md1;
        }
    }
    const float CORR = 1.0f / 128.0f;
    float pcx = g_p1[bi * 2 + 0] + CORR * res[0][0];
    float pcy = g_p1[bi * 2 + 1] + CORR * res[0][1];
    outp[bi * 2 + 0] = pcx;
    outp[bi * 2 + 1] = pcy;
    outp[BN * 2 + bi * 2 + 0] = pcx - p0[bi * 2 + 0];
    outp[BN * 2 + bi * 2 + 1] = pcy - p0[bi * 2 + 1];
    outp[BN * 4 + bi * 4 + 0] = CORR * res[1][0];
    outp[BN * 4 + bi * 4 + 1] = CORR * res[1][1];
    outp[BN * 4 + bi * 4 + 2] = CORR * res[2][0];
    outp[BN * 4 + bi * 4 + 3] = CORR * res[2][1];
}

// ---------------- launch ----------------
extern "C" void kernel_launch(void* const* d_in, const int* in_sizes, int n_in,
                              void* d_out, int out_size) {
    const float* p0_enc  = (const float*)d_in[0];
    const float* v0_enc  = (const float*)d_in[1];
    const float* p0      = (const float*)d_in[2];
    const float* v0      = (const float*)d_in[3];
    const float* a       = (const float*)d_in[4];
    const float* mask    = (const float*)d_in[5];
    const float* lift_c0 = (const float*)d_in[6];
    const float* Wc0     = (const float*)d_in[7];
    const float* lift_d0 = (const float*)d_in[8];
    const float* Wd0     = (const float*)d_in[9];
    const float* Wc1     = (const float*)d_in[10];
    const float* Wd1     = (const float*)d_in[11];
    const float* Wc2     = (const float*)d_in[12];
    const float* Wd2     = (const float*)d_in[13];
    const float* Wc3     = (const float*)d_in[14];
    const float* Wd3     = (const float*)d_in[15];
    const float* Wc4     = (const float*)d_in[16];
    const float* proj_c4 = (const float*)d_in[17];
    const float* Wd4     = (const float*)d_in[18];
    const float* proj_d4 = (const float*)d_in[19];

    lift_kernel<<<BN, 128>>>(p0_enc, v0_enc, p0, v0, a, lift_c0, lift_d0);
    geom_kernel<<<BN, 256>>>(mask, p0, v0, a);
    expand_all<<<(1253376 + 26112 + 255) / 256, 256>>>(Wc0, Wc1, Wc2, Wc3, Wc4,
                                                       Wd0, Wd1, Wd2, Wd3, Wd4);

    const int wOff[5] = {0, 196608, 393216, 786432, 1179648};
    const int dOff[5] = {0, 4096, 8192, 16384, 24576};
    const int smem = GBINS * 128 * 2 * (int)sizeof(float);   // 48KB both configs

    // act ping-pong: L0 writes A; L1 reads A writes B; L2 reads B writes A;
    //                L3 reads A writes B; L4 reads B (no write)
    // layer 0: CK=128, OK=32, mode 0
    stage1_kernel<128, 2><<<BN, 256, smem>>>(0);
    stage2_kernel<32, 4, 2><<<BN / 8, 128>>>(128, 6144, 0, wOff[0], dOff[0], 0, 1);
    // layer 1: CK=64, OK=64, mode 2 (residual), in A -> out B
    stage1_kernel<64, 4><<<BN, 256, smem>>>(1);
    stage2_kernel<64, 2, 4><<<BN / 8, 128>>>(64, 3072, 2, wOff[1], dOff[1], 1, 2);
    // layer 2: CK=64, OK=128, mode 1, in B -> out A
    stage1_kernel<64, 4><<<BN, 256, smem>>>(2);
    stage2_kernel<128, 1, 8><<<BN / 8, 128>>>(64, 3072, 1, wOff[2], dOff[2], 2, 1);
    // layer 3: CK=128, OK=64, mode 1, in A -> out B
    stage1_kernel<128, 2><<<BN, 256, smem>>>(1);
    stage2_kernel<64, 2, 4><<<BN / 8, 128>>>(128, 6144, 1, wOff[3], dOff[3], 1, 2);
    // layer 4: CK=64, OK=24, mode 3, in B
    stage1_kernel<64, 4><<<BN, 256, smem>>>(2);
    stage2_kernel<24, 5, 2><<<BN / 8, 120>>>(64, 3072, 3, wOff[4], dOff[4], 2, 2);

    final_kernel<<<4, 256>>>(p0, proj_c4, proj_d4, (float*)d_out);
}

// round 5
// speedup vs baseline: 3.7605x; 3.6290x over previous
#include <cuda_runtime.h>

#define B_     2
#define NPART  512
#define BN     1024
#define GBINS  48
#define TWO_PI 6.283185307179586f
#define INV_2PI 0.15915494309189535f

// ---------------- static device scratch ----------------
__device__ float    g_p1[BN * 2];
__device__ float    g_regC[BN * 128];
__device__ float    g_regD[BN * 128];
__device__ float4   g_w4c[BN * NPART];
__device__ unsigned g_gc[BN * NPART];
__device__ int      g_jc[BN * NPART];
__device__ int      g_cnt[BN];
__device__ float    g_F[BN * GBINS * 128];
__device__ float    g_out[BN * 128];
__device__ float    g_actA[BN * 128];
__device__ float    g_actB[BN * 128];
__device__ float    g_Wbig[1253376];
__device__ float    g_WdT[26112];
__device__ float    g_part[8 * BN * 128];     // split-K partials (4MB)
__device__ float    g_oc[BN * 24];
__device__ float    g_od[BN * 24];

__constant__ int c_wOff[6] = {0, 196608, 393216, 786432, 1179648, 1253376};
__constant__ int c_dOff[6] = {0, 4096, 8192, 16384, 24576, 26112};

// ---------------- lift: rho1 -> regular rep ----------------
__global__ void lift_kernel(const float* __restrict__ p0_enc,
                            const float* __restrict__ v0_enc,
                            const float* __restrict__ p0,
                            const float* __restrict__ v0,
                            const float* __restrict__ a,
                            const float* __restrict__ lc,
                            const float* __restrict__ ld) {
    int bi = blockIdx.x;
    int tid = threadIdx.x;
    int c = tid >> 3, m = tid & 7;

    float v0x = v0[bi * 2 + 0], v0y = v0[bi * 2 + 1];
    float ax = a[bi * 2 + 0], ay = a[bi * 2 + 1];
    float v1x = v0x + ax, v1y = v0y + ay;
    float p1x = p0[bi * 2 + 0] + 0.5f * (v0x + v1x);
    float p1y = p0[bi * 2 + 1] + 0.5f * (v0y + v1y);

    float x, y;
    if (c == 0)      { x = v1x; y = v1y; }
    else if (c == 1) { x = p1x; y = p1y; }
    else if (c < 9)  { int t = c - 2; x = v0_enc[(bi * 7 + t) * 2 + 0]; y = v0_enc[(bi * 7 + t) * 2 + 1]; }
    else             { int t = c - 9; x = p0_enc[(bi * 7 + t) * 2 + 0]; y = p0_enc[(bi * 7 + t) * 2 + 1]; }

    float th = (float)m * 0.78539816339744831f;
    float cs = cosf(th), sn = sinf(th);
    float lc0 = lc[0], lc1 = lc[1], ld0 = ld[0], ld1 = ld[1];
    g_regC[bi * 128 + tid] = x * (lc0 * cs - lc1 * sn) + y * (lc0 * sn + lc1 * cs);
    g_regD[bi * 128 + tid] = x * (ld0 * cs - ld1 * sn) + y * (ld0 * sn + ld1 * cs);
}

// ---------------- geometry + deterministic compaction ----------------
__global__ void __launch_bounds__(256) geom_kernel(const float* __restrict__ mask,
                                                   const float* __restrict__ p0,
                                                   const float* __restrict__ v0,
                                                   const float* __restrict__ a) {
    __shared__ float sx[NPART], sy[NPART], smk[NPART], sw[NPART];
    __shared__ float red[256];
    __shared__ int warpcnt[8];
    __shared__ int s_base;
    int bi = blockIdx.x;
    int b = bi >> 9, i = bi & 511;
    int tid = threadIdx.x;

    for (int j = tid; j < NPART; j += 256) {
        int gj = b * NPART + j;
        float vx = v0[gj * 2], vy = v0[gj * 2 + 1];
        sx[j] = p0[gj * 2 + 0] + vx + 0.5f * a[gj * 2 + 0];
        sy[j] = p0[gj * 2 + 1] + vy + 0.5f * a[gj * 2 + 1];
        smk[j] = mask[gj];
    }
    __syncthreads();
    if (tid == 0) { g_p1[bi * 2] = sx[i]; g_p1[bi * 2 + 1] = sy[i]; s_base = 0; }
    float xi = sx[i], yi = sy[i];

    float part = 0.f;
    for (int j = tid; j < NPART; j += 256) {
        float rx = sx[j] - xi, ry = sy[j] - yi;
        float d2 = (rx * rx + ry * ry + 1e-12f) * (0.025f * 0.025f);
        float u = fmaxf(1.f - d2, 0.f);
        float w = u * u * u * smk[j];
        sw[j] = w;
        part += w;
    }
    red[tid] = part;
    __syncthreads();
    for (int s = 128; s > 0; s >>= 1) { if (tid < s) red[tid] += red[tid + s]; __syncthreads(); }
    float inv = 1.f / (red[0] + 1e-6f);
    __syncthreads();

    for (int c = 0; c < 2; ++c) {
        int j = c * 256 + tid;
        float w = sw[j];
        bool pred = (w > 0.f);
        unsigned bal = __ballot_sync(0xffffffffu, pred);
        int lane = tid & 31, warp = tid >> 5;
        if (lane == 0) warpcnt[warp] = __popc(bal);
        __syncthreads();
        int base = s_base;
        for (int ww = 0; ww < warp; ++ww) base += warpcnt[ww];
        int pos = base + __popc(bal & ((1u << lane) - 1u));
        if (pred) {
            float rx = sx[j] - xi, ry = sy[j] - yi;
            float d = sqrtf(rx * rx + ry * ry + 1e-12f) * 0.025f;
            float wb = w * inv;
            float rc = fminf(fmaxf(d * 3.f - 0.5f, 0.f), 2.f);
            float r0 = floorf(rc);
            float wr = rc - r0;
            int r0i = (int)r0;
            int r1i = min(r0i + 1, 2);
            float axv = (j == i) ? 1.f : rx;
            float ayv = (j == i) ? 0.f : ry;
            float ang = atan2f(ayv, axv);
            ang = ang - TWO_PI * floorf(ang * INV_2PI);
            float tc = ang * (16.f * INV_2PI);
            float t0 = floorf(tc);
            float wt = tc - t0;
            int t0i = ((int)t0) & 15;
            int t1i = (t0i + 1) & 15;
            int g0 = r0i * 16 + t0i, g1 = r0i * 16 + t1i;
            int g2 = r1i * 16 + t0i, g3 = r1i * 16 + t1i;
            size_t o = (size_t)bi * NPART + pos;
            g_w4c[o] = make_float4((1.f - wr) * (1.f - wt) * wb,
                                   (1.f - wr) * wt * wb,
                                   wr * (1.f - wt) * wb,
                                   wr * wt * wb);
            g_gc[o] = (unsigned)g0 | ((unsigned)g1 << 8) |
                      ((unsigned)g2 << 16) | ((unsigned)g3 << 24);
            g_jc[o] = j;
        }
        __syncthreads();
        if (tid == 0) {
            int t = 0;
            for (int ww = 0; ww < 8; ++ww) t += warpcnt[ww];
            s_base += t;
        }
        __syncthreads();
    }
    if (tid == 0) g_cnt[bi] = s_base;
}

// ---------------- expand all weights ----------------
__global__ void expand_all(const float* __restrict__ Wc0, const float* __restrict__ Wc1,
                           const float* __restrict__ Wc2, const float* __restrict__ Wc3,
                           const float* __restrict__ Wc4,
                           const float* __restrict__ Wd0, const float* __restrict__ Wd1,
                           const float* __restrict__ Wd2, const float* __restrict__ Wd3,
                           const float* __restrict__ Wd4) {
    const int Cs[5] = {16, 8, 8, 16, 8};
    const int Os[5] = {4, 8, 16, 8, 3};
    int idx = blockIdx.x * 256 + threadIdx.x;
    if (idx < 1253376) {
        int l = 0;
        while (idx >= c_wOff[l + 1]) ++l;
        int loc = idx - c_wOff[l];
        const float* Wc = (l == 0) ? Wc0 : (l == 1) ? Wc1 : (l == 2) ? Wc2 : (l == 3) ? Wc3 : Wc4;
        int C = Cs[l], OK = Os[l] * 8;
        int om = loc % OK;
        int kk = loc / OK;
        int n = kk & 7;
        int c = (kk >> 3) % C;
        int g = (kk >> 3) / C;
        int r = g >> 4, t = g & 15;
        int o = om >> 3, m = om & 7;
        g_Wbig[idx] = Wc[(((o * C + c) * 8 + ((n - m) & 7)) * 3 + r) * 16 + ((t - 2 * m) & 15)];
    } else if (idx < 1253376 + 26112) {
        int id2 = idx - 1253376;
        int l = 0;
        while (id2 >= c_dOff[l + 1]) ++l;
        int loc = id2 - c_dOff[l];
        const float* Wd = (l == 0) ? Wd0 : (l == 1) ? Wd1 : (l == 2) ? Wd2 : (l == 3) ? Wd3 : Wd4;
        int C = Cs[l], OK = Os[l] * 8;
        int om = loc % OK;
        int cn = loc / OK;
        int o = om >> 3, m = om & 7, c = cn >> 3, n = cn & 7;
        g_WdT[id2] = Wd[(o * C + c) * 8 + ((m - n) & 7)];
    }
}

// ---------------- stage 1: compacted sparse bin scatter ----------------
// srcsel: 0 = g_regC, 1 = g_actA, 2 = g_actB
template <int CK, int NG>
__global__ void __launch_bounds__(256) stage1_kernel(int srcsel) {
    extern __shared__ float Fs[];
    int bi = blockIdx.x;
    int b = bi >> 9;
    int tid = threadIdx.x;
    int grp = tid / CK, lane = tid % CK;
    const float* __restrict__ feats = (srcsel == 0) ? g_regC : (srcsel == 1) ? g_actA : g_actB;

    for (int x = tid; x < NG * GBINS * CK; x += 256) Fs[x] = 0.f;
    __syncthreads();

    int cnt = g_cnt[bi];
    int k0 = grp * cnt / NG, k1 = (grp + 1) * cnt / NG;
    const float4*   wp = g_w4c + (size_t)bi * NPART;
    const unsigned* gp = g_gc + (size_t)bi * NPART;
    const int*      jp = g_jc + (size_t)bi * NPART;
    const float*    fb = feats + (size_t)b * NPART * CK;
    float* F = Fs + grp * GBINS * CK;

#pragma unroll 2
    for (int k = k0; k < k1; ++k) {
        float4 w = wp[k];
        unsigned g = gp[k];
        float f = fb[jp[k] * CK + lane];
        F[(g & 255u) * CK + lane]         += w.x * f;
        F[((g >> 8) & 255u) * CK + lane]  += w.y * f;
        F[((g >> 16) & 255u) * CK + lane] += w.z * f;
        F[(g >> 24) * CK + lane]          += w.w * f;
    }
    __syncthreads();

    float* out = g_F + (size_t)bi * GBINS * CK;
    for (int x = tid; x < GBINS * CK; x += 256) {
        float s = Fs[x];
#pragma unroll
        for (int c2 = 1; c2 < NG; ++c2) s += Fs[c2 * GBINS * CK + x];
        out[x] = s;
    }
}

// ---------------- stage 2a: split-K tiled GEMM -> partials ----------------
// C_part[ks][bi][om] = sum_{kk in slice ks} F[bi][kk] * Wbig[kk][om]
template <int OK, int TM, int CPT, int KS>
__global__ void __launch_bounds__(TM * OK / CPT) gemm_kernel(int KD, int wOff) {
    const int KB = 32;
    const int THREADS = TM * OK / CPT;
    const int NW4 = (KB * OK / 4 + THREADS - 1) / THREADS;
    const int NF4 = (TM * KB / 4 + THREADS - 1) / THREADS;
    __shared__ float Wt[KB * OK];
    __shared__ float Ft[TM * KB];
    int tid = threadIdx.x;
    int i0 = blockIdx.x * TM;
    int KC = KD / KS;
    int k0 = blockIdx.y * KC;
    int NCH = KC / KB;                       // 24 for all layers

    const float* Wsrc = g_Wbig + wOff + (size_t)k0 * OK;

    float4 wreg[NW4], freg[NF4];
    // prefetch chunk 0
    {
        const float4* src = (const float4*)Wsrc;
#pragma unroll
        for (int u = 0; u < NW4; ++u) {
            int x = tid + u * THREADS;
            if (x < KB * OK / 4) wreg[u] = src[x];
        }
#pragma unroll
        for (int u = 0; u < NF4; ++u) {
            int x = tid + u * THREADS;
            if (x < TM * KB / 4) {
                int row = x / (KB / 4), kc = x % (KB / 4);
                freg[u] = *(const float4*)(g_F + (size_t)(i0 + row) * KD + k0 + kc * 4);
            }
        }
    }

    int row = tid / (OK / CPT);
    int cg = (tid % (OK / CPT)) * CPT;
    float acc[CPT];
#pragma unroll
    for (int c = 0; c < CPT; ++c) acc[c] = 0.f;

    for (int ch = 0; ch < NCH; ++ch) {
        __syncthreads();
#pragma unroll
        for (int u = 0; u < NW4; ++u) {
            int x = tid + u * THREADS;
            if (x < KB * OK / 4) ((float4*)Wt)[x] = wreg[u];
        }
#pragma unroll
        for (int u = 0; u < NF4; ++u) {
            int x = tid + u * THREADS;
            if (x < TM * KB / 4) ((float4*)Ft)[x] = freg[u];
        }
        __syncthreads();
        if (ch + 1 < NCH) {
            const float4* src = (const float4*)(Wsrc + (size_t)(ch + 1) * KB * OK);
#pragma unroll
            for (int u = 0; u < NW4; ++u) {
                int x = tid + u * THREADS;
                if (x < KB * OK / 4) wreg[u] = src[x];
            }
#pragma unroll
            for (int u = 0; u < NF4; ++u) {
                int x = tid + u * THREADS;
                if (x < TM * KB / 4) {
                    int rr = x / (KB / 4), kc = x % (KB / 4);
                    freg[u] = *(const float4*)(g_F + (size_t)(i0 + rr) * KD + k0 + (ch + 1) * KB + kc * 4);
                }
            }
        }
#pragma unroll
        for (int k = 0; k < KB; ++k) {
            float fv = Ft[row * KB + k];
#pragma unroll
            for (int c = 0; c < CPT; c += 4) {
                float4 w = *(const float4*)&Wt[k * OK + cg + c];
                acc[c + 0] = fmaf(fv, w.x, acc[c + 0]);
                acc[c + 1] = fmaf(fv, w.y, acc[c + 1]);
                acc[c + 2] = fmaf(fv, w.z, acc[c + 2]);
                acc[c + 3] = fmaf(fv, w.w, acc[c + 3]);
            }
        }
    }

    float* dst = g_part + ((size_t)blockIdx.y * BN + i0 + row) * OK + cg;
#pragma unroll
    for (int c = 0; c < CPT; ++c) dst[c] = acc[c];
}

// ---------------- stage 2b: deterministic reduce + dense + epilogue ----------------
// modes: 0 = concat (L0), 1 = sum, 2 = sum + residual, 3 = last (write oc/od)
template <int OK, int ROWS>
__global__ void __launch_bounds__(OK * ROWS) reduce_kernel(int KS, int CK, int mode,
                                                           int dOff, int ain, int aout) {
    int tid = threadIdx.x;
    int row = tid / OK, om = tid % OK;
    int bi = blockIdx.x * ROWS + row;

    float oc = 0.f;
    for (int ks = 0; ks < KS; ++ks)
        oc += g_part[((size_t)ks * BN + bi) * OK + om];

    const float* __restrict__ densein = (ain == 0) ? g_regD : (ain == 1) ? g_actA : g_actB;
    float* __restrict__ actout = (aout == 1) ? g_actA : g_actB;
    const float* WdT = g_WdT + dOff;
    const float* x = densein + (size_t)bi * CK;
    float od = 0.f;
    for (int cn = 0; cn < CK; ++cn) od = fmaf(x[cn], WdT[cn * OK + om], od);

    if (mode == 0) {
        g_out[bi * 64 + om] = oc;
        g_out[bi * 64 + 32 + om] = od;
        float sc = oc * oc;
        sc += __shfl_xor_sync(0xffffffffu, sc, 1);
        sc += __shfl_xor_sync(0xffffffffu, sc, 2);
        sc += __shfl_xor_sync(0xffffffffu, sc, 4);
        float mc = sc + 1e-6f;
        actout[bi * 64 + om] = oc / mc * fmaxf(mc - 0.2f, 0.f);
        float sd = od * od;
        sd += __shfl_xor_sync(0xffffffffu, sd, 1);
        sd += __shfl_xor_sync(0xffffffffu, sd, 2);
        sd += __shfl_xor_sync(0xffffffffu, sd, 4);
        float md = sd + 1e-6f;
        actout[bi * 64 + 32 + om] = od / md * fmaxf(md - 0.2f, 0.f);
    } else if (mode == 3) {
        g_oc[bi * 24 + om] = oc;
        g_od[bi * 24 + om] = od;
    } else {
        float v = oc + od;
        if (mode == 2) v += g_out[bi * OK + om];
        g_out[bi * OK + om] = v;
        float sq = v * v;
        sq += __shfl_xor_sync(0xffffffffu, sq, 1);
        sq += __shfl_xor_sync(0xffffffffu, sq, 2);
        sq += __shfl_xor_sync(0xffffffffu, sq, 4);
        float mg = sq + 1e-6f;
        actout[bi * OK + om] = v / mg * fmaxf(mg - 0.2f, 0.f);
    }
}

// ---------------- final projection + correction ----------------
__global__ void final_kernel(const float* __restrict__ p0,
                             const float* __restrict__ pc,
                             const float* __restrict__ pd,
                             float* __restrict__ outp) {
    int bi = blockIdx.x * blockDim.x + threadIdx.x;
    if (bi >= BN) return;
    float res[3][2] = {{0.f, 0.f}, {0.f, 0.f}, {0.f, 0.f}};
    float c0 = pc[0], c1 = pc[1], d0 = pd[0], d1 = pd[1];
#pragma unroll
    for (int m = 0; m < 8; ++m) {
        float th = (float)m * 0.78539816339744831f;
        float cs = cosf(th), sn = sinf(th);
        float Mc0 = c0 * cs - c1 * sn, Mc1 = c0 * sn + c1 * cs;
        float Md0 = d0 * cs - d1 * sn, Md1 = d0 * sn + d1 * cs;
#pragma unroll
        for (int ch = 0; ch < 3; ++ch) {
            float vc = g_oc[bi * 24 + ch * 8 + m];
            float vd = g_od[bi * 24 + ch * 8 + m];
            res[ch][0] += vc * Mc0 + vd * Md0;
            res[ch][1] += vc * Mc1 + vd * Md1;
        }
    }
    const float CORR = 1.0f / 128.0f;
    float pcx = g_p1[bi * 2 + 0] + CORR * res[0][0];
    float pcy = g_p1[bi * 2 + 1] + CORR * res[0][1];
    outp[bi * 2 + 0] = pcx;
    outp[bi * 2 + 1] = pcy;
    outp[BN * 2 + bi * 2 + 0] = pcx - p0[bi * 2 + 0];
    outp[BN * 2 + bi * 2 + 1] = pcy - p0[bi * 2 + 1];
    outp[BN * 4 + bi * 4 + 0] = CORR * res[1][0];
    outp[BN * 4 + bi * 4 + 1] = CORR * res[1][1];
    outp[BN * 4 + bi * 4 + 2] = CORR * res[2][0];
    outp[BN * 4 + bi * 4 + 3] = CORR * res[2][1];
}

// ---------------- launch ----------------
extern "C" void kernel_launch(void* const* d_in, const int* in_sizes, int n_in,
                              void* d_out, int out_size) {
    const float* p0_enc  = (const float*)d_in[0];
    const float* v0_enc  = (const float*)d_in[1];
    const float* p0      = (const float*)d_in[2];
    const float* v0      = (const float*)d_in[3];
    const float* a       = (const float*)d_in[4];
    const float* mask    = (const float*)d_in[5];
    const float* lift_c0 = (const float*)d_in[6];
    const float* Wc0     = (const float*)d_in[7];
    const float* lift_d0 = (const float*)d_in[8];
    const float* Wd0     = (const float*)d_in[9];
    const float* Wc1     = (const float*)d_in[10];
    const float* Wd1     = (const float*)d_in[11];
    const float* Wc2     = (const float*)d_in[12];
    const float* Wd2     = (const float*)d_in[13];
    const float* Wc3     = (const float*)d_in[14];
    const float* Wd3     = (const float*)d_in[15];
    const float* Wc4     = (const float*)d_in[16];
    const float* proj_c4 = (const float*)d_in[17];
    const float* Wd4     = (const float*)d_in[18];
    const float* proj_d4 = (const float*)d_in[19];

    lift_kernel<<<BN, 128>>>(p0_enc, v0_enc, p0, v0, a, lift_c0, lift_d0);
    geom_kernel<<<BN, 256>>>(mask, p0, v0, a);
    expand_all<<<(1253376 + 26112 + 255) / 256, 256>>>(Wc0, Wc1, Wc2, Wc3, Wc4,
                                                       Wd0, Wd1, Wd2, Wd3, Wd4);

    const int wOff[5] = {0, 196608, 393216, 786432, 1179648};
    const int dOff[5] = {0, 4096, 8192, 16384, 24576};
    const int smem = GBINS * 128 * 2 * (int)sizeof(float);   // 48KB

    // act ping-pong: L0 -> A; L1: A->B; L2: B->A; L3: A->B; L4: reads B
    // L0: CK=128, OK=32, KD=6144
    stage1_kernel<128, 2><<<BN, 256, smem>>>(0);
    gemm_kernel<32, 32, 4, 8><<<dim3(32, 8), 256>>>(6144, wOff[0]);
    reduce_kernel<32, 8><<<BN / 8, 256>>>(8, 128, 0, dOff[0], 0, 1);
    // L1: CK=64, OK=64, KD=3072, residual
    stage1_kernel<64, 4><<<BN, 256, smem>>>(1);
    gemm_kernel<64, 16, 4, 4><<<dim3(64, 4), 256>>>(3072, wOff[1]);
    reduce_kernel<64, 4><<<BN / 4, 256>>>(4, 64, 2, dOff[1], 1, 2);
    // L2: CK=64, OK=128, KD=3072
    stage1_kernel<64, 4><<<BN, 256, smem>>>(2);
    gemm_kernel<128, 16, 8, 4><<<dim3(64, 4), 256>>>(3072, wOff[2]);
    reduce_kernel<128, 2><<<BN / 2, 256>>>(4, 64, 1, dOff[2], 2, 1);
    // L3: CK=128, OK=64, KD=6144
    stage1_kernel<128, 2><<<BN, 256, smem>>>(1);
    gemm_kernel<64, 16, 4, 8><<<dim3(64, 8), 256>>>(6144, wOff[3]);
    reduce_kernel<64, 4><<<BN / 4, 256>>>(8, 128, 1, dOff[3], 1, 2);
    // L4: CK=64, OK=24, KD=3072, last
    stage1_kernel<64, 4><<<BN, 256, smem>>>(2);
    gemm_kernel<24, 32, 4, 4><<<dim3(32, 4), 192>>>(3072, wOff[4]);
    reduce_kernel<24, 8><<<BN / 8, 192>>>(4, 64, 3, dOff[4], 2, 2);

    final_kernel<<<4, 256>>>(p0, proj_c4, proj_d4, (float*)d_out);
}

// round 6
// speedup vs baseline: 4.6575x; 1.2385x over previous
#include <cuda_runtime.h>

#define B_     2
#define NPART  512
#define BN     1024
#define GBINS  48
#define TWO_PI 6.283185307179586f
#define INV_2PI 0.15915494309189535f

// ---------------- static device scratch ----------------
__device__ float    g_p1[BN * 2];
__device__ float    g_regC[BN * 128];
__device__ float    g_regD[BN * 128];
__device__ float2   g_ent[BN * 2048];         // CSR entries per particle: (w, j-as-bits)
__device__ int      g_binStart[BN * 49];      // CSR row pointers (48 bins + end)
__device__ float    g_F[BN * GBINS * 128];
__device__ float    g_out[BN * 128];
__device__ float    g_actA[BN * 128];
__device__ float    g_actB[BN * 128];
__device__ float    g_Wbig[1253376];
__device__ float    g_WdT[26112];
__device__ float    g_part[8 * BN * 128];     // split-K partials
__device__ float    g_oc[BN * 24];
__device__ float    g_od[BN * 24];

__constant__ int c_wOff[6] = {0, 196608, 393216, 786432, 1179648, 1253376};
__constant__ int c_dOff[6] = {0, 4096, 8192, 16384, 24576, 26112};

// ---------------- lift: rho1 -> regular rep ----------------
__global__ void lift_kernel(const float* __restrict__ p0_enc,
                            const float* __restrict__ v0_enc,
                            const float* __restrict__ p0,
                            const float* __restrict__ v0,
                            const float* __restrict__ a,
                            const float* __restrict__ lc,
                            const float* __restrict__ ld) {
    int bi = blockIdx.x;
    int tid = threadIdx.x;
    int c = tid >> 3, m = tid & 7;

    float v0x = v0[bi * 2 + 0], v0y = v0[bi * 2 + 1];
    float ax = a[bi * 2 + 0], ay = a[bi * 2 + 1];
    float v1x = v0x + ax, v1y = v0y + ay;
    float p1x = p0[bi * 2 + 0] + 0.5f * (v0x + v1x);
    float p1y = p0[bi * 2 + 1] + 0.5f * (v0y + v1y);

    float x, y;
    if (c == 0)      { x = v1x; y = v1y; }
    else if (c == 1) { x = p1x; y = p1y; }
    else if (c < 9)  { int t = c - 2; x = v0_enc[(bi * 7 + t) * 2 + 0]; y = v0_enc[(bi * 7 + t) * 2 + 1]; }
    else             { int t = c - 9; x = p0_enc[(bi * 7 + t) * 2 + 0]; y = p0_enc[(bi * 7 + t) * 2 + 1]; }

    float th = (float)m * 0.78539816339744831f;
    float cs = cosf(th), sn = sinf(th);
    float lc0 = lc[0], lc1 = lc[1], ld0 = ld[0], ld1 = ld[1];
    g_regC[bi * 128 + tid] = x * (lc0 * cs - lc1 * sn) + y * (lc0 * sn + lc1 * cs);
    g_regD[bi * 128 + tid] = x * (ld0 * cs - ld1 * sn) + y * (ld0 * sn + ld1 * cs);
}

// ---------------- geometry -> per-particle CSR over 48 bins ----------------
__global__ void __launch_bounds__(256) geom_kernel(const float* __restrict__ mask,
                                                   const float* __restrict__ p0,
                                                   const float* __restrict__ v0,
                                                   const float* __restrict__ a) {
    __shared__ float sx[NPART], sy[NPART], smk[NPART], sw[NPART];
    __shared__ float red[256];
    __shared__ int cnt[GBINS], offs[GBINS], bstart[GBINS + 1];
    int bi = blockIdx.x;
    int b = bi >> 9, i = bi & 511;
    int tid = threadIdx.x;

    for (int j = tid; j < NPART; j += 256) {
        int gj = b * NPART + j;
        float vx = v0[gj * 2], vy = v0[gj * 2 + 1];
        sx[j] = p0[gj * 2 + 0] + vx + 0.5f * a[gj * 2 + 0];
        sy[j] = p0[gj * 2 + 1] + vy + 0.5f * a[gj * 2 + 1];
        smk[j] = mask[gj];
    }
    if (tid < GBINS) cnt[tid] = 0;
    __syncthreads();
    if (tid == 0) { g_p1[bi * 2] = sx[i]; g_p1[bi * 2 + 1] = sy[i]; }
    float xi = sx[i], yi = sy[i];

    float part = 0.f;
    for (int j = tid; j < NPART; j += 256) {
        float rx = sx[j] - xi, ry = sy[j] - yi;
        float d2 = (rx * rx + ry * ry + 1e-12f) * (0.025f * 0.025f);
        float u = fmaxf(1.f - d2, 0.f);
        float w = u * u * u * smk[j];
        sw[j] = w;
        part += w;
    }
    red[tid] = part;
    __syncthreads();
    for (int s = 128; s > 0; s >>= 1) { if (tid < s) red[tid] += red[tid + s]; __syncthreads(); }
    float inv = 1.f / (red[0] + 1e-6f);
    __syncthreads();

    // per-thread local entries (2 j's per thread)
    float wloc[2][4];
    unsigned gloc[2];
    int jloc[2];
    int nloc = 0;
#pragma unroll
    for (int c = 0; c < 2; ++c) {
        int j = c * 256 + tid;
        float w = sw[j];
        if (w > 0.f) {
            float rx = sx[j] - xi, ry = sy[j] - yi;
            float d = sqrtf(rx * rx + ry * ry + 1e-12f) * 0.025f;
            float wb = w * inv;
            float rc = fminf(fmaxf(d * 3.f - 0.5f, 0.f), 2.f);
            float r0 = floorf(rc);
            float wr = rc - r0;
            int r0i = (int)r0;
            int r1i = min(r0i + 1, 2);
            float axv = (j == i) ? 1.f : rx;
            float ayv = (j == i) ? 0.f : ry;
            float ang = atan2f(ayv, axv);
            ang = ang - TWO_PI * floorf(ang * INV_2PI);
            float tc = ang * (16.f * INV_2PI);
            float t0 = floorf(tc);
            float wt = tc - t0;
            int t0i = ((int)t0) & 15;
            int t1i = (t0i + 1) & 15;
            int g0 = r0i * 16 + t0i, g1 = r0i * 16 + t1i;
            int g2 = r1i * 16 + t0i, g3 = r1i * 16 + t1i;
            wloc[nloc][0] = (1.f - wr) * (1.f - wt) * wb;
            wloc[nloc][1] = (1.f - wr) * wt * wb;
            wloc[nloc][2] = wr * (1.f - wt) * wb;
            wloc[nloc][3] = wr * wt * wb;
            gloc[nloc] = (unsigned)g0 | ((unsigned)g1 << 8) |
                         ((unsigned)g2 << 16) | ((unsigned)g3 << 24);
            jloc[nloc] = j;
            ++nloc;
            atomicAdd(&cnt[g0], 1);
            atomicAdd(&cnt[g1], 1);
            atomicAdd(&cnt[g2], 1);
            atomicAdd(&cnt[g3], 1);
        }
    }
    __syncthreads();
    if (tid == 0) {
        int s = 0;
        for (int g = 0; g < GBINS; ++g) { bstart[g] = s; s += cnt[g]; }
        bstart[GBINS] = s;
    }
    __syncthreads();
    if (tid < GBINS) offs[tid] = bstart[tid];
    if (tid < GBINS + 1) g_binStart[bi * 49 + tid] = bstart[tid];
    __syncthreads();

    float2* ent = g_ent + (size_t)bi * 2048;
    for (int l = 0; l < nloc; ++l) {
        unsigned gp = gloc[l];
        float fj = __int_as_float(jloc[l]);
#pragma unroll
        for (int s = 0; s < 4; ++s) {
            int g = (gp >> (8 * s)) & 255;
            int pos = atomicAdd(&offs[g], 1);
            ent[pos] = make_float2(wloc[l][s], fj);
        }
    }
}

// ---------------- expand all weights ----------------
__global__ void expand_all(const float* __restrict__ Wc0, const float* __restrict__ Wc1,
                           const float* __restrict__ Wc2, const float* __restrict__ Wc3,
                           const float* __restrict__ Wc4,
                           const float* __restrict__ Wd0, const float* __restrict__ Wd1,
                           const float* __restrict__ Wd2, const float* __restrict__ Wd3,
                           const float* __restrict__ Wd4) {
    const int Cs[5] = {16, 8, 8, 16, 8};
    const int Os[5] = {4, 8, 16, 8, 3};
    int idx = blockIdx.x * 256 + threadIdx.x;
    if (idx < 1253376) {
        int l = 0;
        while (idx >= c_wOff[l + 1]) ++l;
        int loc = idx - c_wOff[l];
        const float* Wc = (l == 0) ? Wc0 : (l == 1) ? Wc1 : (l == 2) ? Wc2 : (l == 3) ? Wc3 : Wc4;
        int C = Cs[l], OK = Os[l] * 8;
        int om = loc % OK;
        int kk = loc / OK;
        int n = kk & 7;
        int c = (kk >> 3) % C;
        int g = (kk >> 3) / C;
        int r = g >> 4, t = g & 15;
        int o = om >> 3, m = om & 7;
        g_Wbig[idx] = Wc[(((o * C + c) * 8 + ((n - m) & 7)) * 3 + r) * 16 + ((t - 2 * m) & 15)];
    } else if (idx < 1253376 + 26112) {
        int id2 = idx - 1253376;
        int l = 0;
        while (id2 >= c_dOff[l + 1]) ++l;
        int loc = id2 - c_dOff[l];
        const float* Wd = (l == 0) ? Wd0 : (l == 1) ? Wd1 : (l == 2) ? Wd2 : (l == 3) ? Wd3 : Wd4;
        int C = Cs[l], OK = Os[l] * 8;
        int om = loc % OK;
        int cn = loc / OK;
        int o = om >> 3, m = om & 7, c = cn >> 3, n = cn & 7;
        g_WdT[id2] = Wd[(o * C + c) * 8 + ((m - n) & 7)];
    }
}

// ---------------- stage 1: CSR gather F[i,g,:] = sum_entries w * feats[j,:] ----------------
// srcsel: 0 = g_regC, 1 = g_actA, 2 = g_actB. One warp per bin (8 warps cycle 48 bins).
template <int CK>
__global__ void __launch_bounds__(256) stage1_kernel(int srcsel) {
    const int VEC = CK / 32;                 // 4 (CK=128) or 2 (CK=64)
    int bi = blockIdx.x;
    int b = bi >> 9;
    int tid = threadIdx.x;
    int warp = tid >> 5, lane = tid & 31;
    const float* __restrict__ feats = (srcsel == 0) ? g_regC : (srcsel == 1) ? g_actA : g_actB;

    __shared__ int bs[GBINS + 1];
    if (tid < GBINS + 1) bs[tid] = g_binStart[bi * 49 + tid];
    __syncthreads();

    const float2* __restrict__ ent = g_ent + (size_t)bi * 2048;
    const float* __restrict__ fb = feats + (size_t)b * NPART * CK;

    for (int g = warp; g < GBINS; g += 8) {
        int s = bs[g], e = bs[g + 1];
        float acc[VEC];
#pragma unroll
        for (int v = 0; v < VEC; ++v) acc[v] = 0.f;

        int k = s;
        if (VEC == 4) {
            float4 a0, a1;
            for (; k + 2 <= e; k += 2) {
                float2 m0 = ent[k], m1 = ent[k + 1];
                a0 = *(const float4*)(fb + __float_as_int(m0.y) * CK + lane * 4);
                a1 = *(const float4*)(fb + __float_as_int(m1.y) * CK + lane * 4);
                acc[0] = fmaf(m0.x, a0.x, acc[0]);
                acc[1] = fmaf(m0.x, a0.y, acc[1]);
                acc[2] = fmaf(m0.x, a0.z, acc[2]);
                acc[3] = fmaf(m0.x, a0.w, acc[3]);
                acc[0] = fmaf(m1.x, a1.x, acc[0]);
                acc[1] = fmaf(m1.x, a1.y, acc[1]);
                acc[2] = fmaf(m1.x, a1.z, acc[2]);
                acc[3] = fmaf(m1.x, a1.w, acc[3]);
            }
            if (k < e) {
                float2 m0 = ent[k];
                a0 = *(const float4*)(fb + __float_as_int(m0.y) * CK + lane * 4);
                acc[0] = fmaf(m0.x, a0.x, acc[0]);
                acc[1] = fmaf(m0.x, a0.y, acc[1]);
                acc[2] = fmaf(m0.x, a0.z, acc[2]);
                acc[3] = fmaf(m0.x, a0.w, acc[3]);
            }
            float4 r = make_float4(acc[0], acc[1], acc[2], acc[3]);
            *(float4*)(g_F + (size_t)bi * GBINS * CK + g * CK + lane * 4) = r;
        } else {
            float2 a0, a1;
            for (; k + 2 <= e; k += 2) {
                float2 m0 = ent[k], m1 = ent[k + 1];
                a0 = *(const float2*)(fb + __float_as_int(m0.y) * CK + lane * 2);
                a1 = *(const float2*)(fb + __float_as_int(m1.y) * CK + lane * 2);
                acc[0] = fmaf(m0.x, a0.x, acc[0]);
                acc[1] = fmaf(m0.x, a0.y, acc[1]);
                acc[0] = fmaf(m1.x, a1.x, acc[0]);
                acc[1] = fmaf(m1.x, a1.y, acc[1]);
            }
            if (k < e) {
                float2 m0 = ent[k];
                a0 = *(const float2*)(fb + __float_as_int(m0.y) * CK + lane * 2);
                acc[0] = fmaf(m0.x, a0.x, acc[0]);
                acc[1] = fmaf(m0.x, a0.y, acc[1]);
            }
            float2 r = make_float2(acc[0], acc[1]);
            *(float2*)(g_F + (size_t)bi * GBINS * CK + g * CK + lane * 2) = r;
        }
    }
}

// ---------------- stage 2a: split-K tiled GEMM -> partials ----------------
template <int OK, int TM, int CPT, int KS>
__global__ void __launch_bounds__(TM * OK / CPT) gemm_kernel(int KD, int wOff) {
    const int KB = 32;
    const int THREADS = TM * OK / CPT;
    const int NW4 = (KB * OK / 4 + THREADS - 1) / THREADS;
    const int NF4 = (TM * KB / 4 + THREADS - 1) / THREADS;
    __shared__ float Wt[KB * OK];
    __shared__ float Ft[TM * KB];
    int tid = threadIdx.x;
    int i0 = blockIdx.x * TM;
    int KC = KD / KS;
    int k0 = blockIdx.y * KC;
    int NCH = KC / KB;

    const float* Wsrc = g_Wbig + wOff + (size_t)k0 * OK;

    float4 wreg[NW4], freg[NF4];
    {
        const float4* src = (const float4*)Wsrc;
#pragma unroll
        for (int u = 0; u < NW4; ++u) {
            int x = tid + u * THREADS;
            if (x < KB * OK / 4) wreg[u] = src[x];
        }
#pragma unroll
        for (int u = 0; u < NF4; ++u) {
            int x = tid + u * THREADS;
            if (x < TM * KB / 4) {
                int row = x / (KB / 4), kc = x % (KB / 4);
                freg[u] = *(const float4*)(g_F + (size_t)(i0 + row) * KD + k0 + kc * 4);
            }
        }
    }

    int row = tid / (OK / CPT);
    int cg = (tid % (OK / CPT)) * CPT;
    float acc[CPT];
#pragma unroll
    for (int c = 0; c < CPT; ++c) acc[c] = 0.f;

    for (int ch = 0; ch < NCH; ++ch) {
        __syncthreads();
#pragma unroll
        for (int u = 0; u < NW4; ++u) {
            int x = tid + u * THREADS;
            if (x < KB * OK / 4) ((float4*)Wt)[x] = wreg[u];
        }
#pragma unroll
        for (int u = 0; u < NF4; ++u) {
            int x = tid + u * THREADS;
            if (x < TM * KB / 4) ((float4*)Ft)[x] = freg[u];
        }
        __syncthreads();
        if (ch + 1 < NCH) {
            const float4* src = (const float4*)(Wsrc + (size_t)(ch + 1) * KB * OK);
#pragma unroll
            for (int u = 0; u < NW4; ++u) {
                int x = tid + u * THREADS;
                if (x < KB * OK / 4) wreg[u] = src[x];
            }
#pragma unroll
            for (int u = 0; u < NF4; ++u) {
                int x = tid + u * THREADS;
                if (x < TM * KB / 4) {
                    int rr = x / (KB / 4), kc = x % (KB / 4);
                    freg[u] = *(const float4*)(g_F + (size_t)(i0 + rr) * KD + k0 + (ch + 1) * KB + kc * 4);
                }
            }
        }
#pragma unroll
        for (int k = 0; k < KB; ++k) {
            float fv = Ft[row * KB + k];
#pragma unroll
            for (int c = 0; c < CPT; c += 4) {
                float4 w = *(const float4*)&Wt[k * OK + cg + c];
                acc[c + 0] = fmaf(fv, w.x, acc[c + 0]);
                acc[c + 1] = fmaf(fv, w.y, acc[c + 1]);
                acc[c + 2] = fmaf(fv, w.z, acc[c + 2]);
                acc[c + 3] = fmaf(fv, w.w, acc[c + 3]);
            }
        }
    }

    float* dst = g_part + ((size_t)blockIdx.y * BN + i0 + row) * OK + cg;
#pragma unroll
    for (int c = 0; c < CPT; ++c) dst[c] = acc[c];
}

// ---------------- stage 2b: deterministic reduce + dense + epilogue ----------------
template <int OK, int ROWS>
__global__ void __launch_bounds__(OK * ROWS) reduce_kernel(int KS, int CK, int mode,
                                                           int dOff, int ain, int aout) {
    int tid = threadIdx.x;
    int row = tid / OK, om = tid % OK;
    int bi = blockIdx.x * ROWS + row;

    float oc = 0.f;
    for (int ks = 0; ks < KS; ++ks)
        oc += g_part[((size_t)ks * BN + bi) * OK + om];

    const float* __restrict__ densein = (ain == 0) ? g_regD : (ain == 1) ? g_actA : g_actB;
    float* __restrict__ actout = (aout == 1) ? g_actA : g_actB;
    const float* WdT = g_WdT + dOff;
    const float* x = densein + (size_t)bi * CK;
    float od = 0.f;
    for (int cn = 0; cn < CK; ++cn) od = fmaf(x[cn], WdT[cn * OK + om], od);

    if (mode == 0) {
        g_out[bi * 64 + om] = oc;
        g_out[bi * 64 + 32 + om] = od;
        float sc = oc * oc;
        sc += __shfl_xor_sync(0xffffffffu, sc, 1);
        sc += __shfl_xor_sync(0xffffffffu, sc, 2);
        sc += __shfl_xor_sync(0xffffffffu, sc, 4);
        float mc = sc + 1e-6f;
        actout[bi * 64 + om] = oc / mc * fmaxf(mc - 0.2f, 0.f);
        float sd = od * od;
        sd += __shfl_xor_sync(0xffffffffu, sd, 1);
        sd += __shfl_xor_sync(0xffffffffu, sd, 2);
        sd += __shfl_xor_sync(0xffffffffu, sd, 4);
        float md = sd + 1e-6f;
        actout[bi * 64 + 32 + om] = od / md * fmaxf(md - 0.2f, 0.f);
    } else if (mode == 3) {
        g_oc[bi * 24 + om] = oc;
        g_od[bi * 24 + om] = od;
    } else {
        float v = oc + od;
        if (mode == 2) v += g_out[bi * OK + om];
        g_out[bi * OK + om] = v;
        float sq = v * v;
        sq += __shfl_xor_sync(0xffffffffu, sq, 1);
        sq += __shfl_xor_sync(0xffffffffu, sq, 2);
        sq += __shfl_xor_sync(0xffffffffu, sq, 4);
        float mg = sq + 1e-6f;
        actout[bi * OK + om] = v / mg * fmaxf(mg - 0.2f, 0.f);
    }
}

// ---------------- final projection + correction ----------------
__global__ void final_kernel(const float* __restrict__ p0,
                             const float* __restrict__ pc,
                             const float* __restrict__ pd,
                             float* __restrict__ outp) {
    int bi = blockIdx.x * blockDim.x + threadIdx.x;
    if (bi >= BN) return;
    float res[3][2] = {{0.f, 0.f}, {0.f, 0.f}, {0.f, 0.f}};
    float c0 = pc[0], c1 = pc[1], d0 = pd[0], d1 = pd[1];
#pragma unroll
    for (int m = 0; m < 8; ++m) {
        float th = (float)m * 0.78539816339744831f;
        float cs = cosf(th), sn = sinf(th);
        float Mc0 = c0 * cs - c1 * sn, Mc1 = c0 * sn + c1 * cs;
        float Md0 = d0 * cs - d1 * sn, Md1 = d0 * sn + d1 * cs;
#pragma unroll
        for (int ch = 0; ch < 3; ++ch) {
            float vc = g_oc[bi * 24 + ch * 8 + m];
            float vd = g_od[bi * 24 + ch * 8 + m];
            res[ch][0] += vc * Mc0 + vd * Md0;
            res[ch][1] += vc * Mc1 + vd * Md1;
        }
    }
    const float CORR = 1.0f / 128.0f;
    float pcx = g_p1[bi * 2 + 0] + CORR * res[0][0];
    float pcy = g_p1[bi * 2 + 1] + CORR * res[0][1];
    outp[bi * 2 + 0] = pcx;
    outp[bi * 2 + 1] = pcy;
    outp[BN * 2 + bi * 2 + 0] = pcx - p0[bi * 2 + 0];
    outp[BN * 2 + bi * 2 + 1] = pcy - p0[bi * 2 + 1];
    outp[BN * 4 + bi * 4 + 0] = CORR * res[1][0];
    outp[BN * 4 + bi * 4 + 1] = CORR * res[1][1];
    outp[BN * 4 + bi * 4 + 2] = CORR * res[2][0];
    outp[BN * 4 + bi * 4 + 3] = CORR * res[2][1];
}

// ---------------- launch ----------------
extern "C" void kernel_launch(void* const* d_in, const int* in_sizes, int n_in,
                              void* d_out, int out_size) {
    const float* p0_enc  = (const float*)d_in[0];
    const float* v0_enc  = (const float*)d_in[1];
    const float* p0      = (const float*)d_in[2];
    const float* v0      = (const float*)d_in[3];
    const float* a       = (const float*)d_in[4];
    const float* mask    = (const float*)d_in[5];
    const float* lift_c0 = (const float*)d_in[6];
    const float* Wc0     = (const float*)d_in[7];
    const float* lift_d0 = (const float*)d_in[8];
    const float* Wd0     = (const float*)d_in[9];
    const float* Wc1     = (const float*)d_in[10];
    const float* Wd1     = (const float*)d_in[11];
    const float* Wc2     = (const float*)d_in[12];
    const float* Wd2     = (const float*)d_in[13];
    const float* Wc3     = (const float*)d_in[14];
    const float* Wd3     = (const float*)d_in[15];
    const float* Wc4     = (const float*)d_in[16];
    const float* proj_c4 = (const float*)d_in[17];
    const float* Wd4     = (const float*)d_in[18];
    const float* proj_d4 = (const float*)d_in[19];

    lift_kernel<<<BN, 128>>>(p0_enc, v0_enc, p0, v0, a, lift_c0, lift_d0);
    geom_kernel<<<BN, 256>>>(mask, p0, v0, a);
    expand_all<<<(1253376 + 26112 + 255) / 256, 256>>>(Wc0, Wc1, Wc2, Wc3, Wc4,
                                                       Wd0, Wd1, Wd2, Wd3, Wd4);

    const int wOff[5] = {0, 196608, 393216, 786432, 1179648};
    const int dOff[5] = {0, 4096, 8192, 16384, 24576};

    // act ping-pong: L0 -> A; L1: A->B; L2: B->A; L3: A->B; L4: reads B
    // L0: CK=128, OK=32, KD=6144
    stage1_kernel<128><<<BN, 256>>>(0);
    gemm_kernel<32, 32, 4, 8><<<dim3(32, 8), 256>>>(6144, wOff[0]);
    reduce_kernel<32, 8><<<BN / 8, 256>>>(8, 128, 0, dOff[0], 0, 1);
    // L1: CK=64, OK=64, KD=3072, residual
    stage1_kernel<64><<<BN, 256>>>(1);
    gemm_kernel<64, 16, 4, 4><<<dim3(64, 4), 256>>>(3072, wOff[1]);
    reduce_kernel<64, 4><<<BN / 4, 256>>>(4, 64, 2, dOff[1], 1, 2);
    // L2: CK=64, OK=128, KD=3072
    stage1_kernel<64><<<BN, 256>>>(2);
    gemm_kernel<128, 16, 8, 4><<<dim3(64, 4), 256>>>(3072, wOff[2]);
    reduce_kernel<128, 2><<<BN / 2, 256>>>(4, 64, 1, dOff[2], 2, 1);
    // L3: CK=128, OK=64, KD=6144
    stage1_kernel<128><<<BN, 256>>>(1);
    gemm_kernel<64, 16, 4, 8><<<dim3(64, 8), 256>>>(6144, wOff[3]);
    reduce_kernel<64, 4><<<BN / 4, 256>>>(8, 128, 1, dOff[3], 1, 2);
    // L4: CK=64, OK=24, KD=3072, last
    stage1_kernel<64><<<BN, 256>>>(2);
    gemm_kernel<24, 32, 4, 4><<<dim3(32, 4), 192>>>(3072, wOff[4]);
    reduce_kernel<24, 8><<<BN / 8, 192>>>(4, 64, 3, dOff[4], 2, 2);

    final_kernel<<<4, 256>>>(p0, proj_c4, proj_d4, (float*)d_out);
}

// round 7
// speedup vs baseline: 5.2840x; 1.1345x over previous
#include <cuda_runtime.h>

#define B_     2
#define NPART  512
#define BN     1024
#define GBINS  48
#define TWO_PI 6.283185307179586f
#define INV_2PI 0.15915494309189535f

// ---------------- static device scratch ----------------
__device__ float    g_p1[BN * 2];
__device__ float    g_regC[BN * 128];
__device__ float    g_regD[BN * 128];
__device__ float4   g_ent[BN * 512];          // one entry per neighbor: (wb(1-wr), wb*wr, wt, j|r0<<16)
__device__ int      g_binStart[BN * 17];      // CSR over 16 t-columns
__device__ float    g_F[BN * GBINS * 128];
__device__ float    g_out[BN * 128];
__device__ float    g_actA[BN * 128];
__device__ float    g_actB[BN * 128];
__device__ float    g_Wbig[1253376];
__device__ float    g_WdT[26112];
__device__ float    g_part[8 * BN * 128];     // split-K partials (1M floats)
__device__ float    g_oc[BN * 24];
__device__ float    g_od[BN * 24];

__constant__ int c_wOff[6] = {0, 196608, 393216, 786432, 1179648, 1253376};
__constant__ int c_dOff[6] = {0, 4096, 8192, 16384, 24576, 26112};

// ---------------- f32x2 helpers ----------------
__device__ __forceinline__ unsigned long long pack2(float x) {
    unsigned long long r;
    asm("mov.b64 %0, {%1, %1};" : "=l"(r) : "f"(x));
    return r;
}
__device__ __forceinline__ unsigned long long ffma2(unsigned long long a,
                                                    unsigned long long b,
                                                    unsigned long long c) {
    unsigned long long d;
    asm("fma.rn.f32x2 %0, %1, %2, %3;" : "=l"(d) : "l"(a), "l"(b), "l"(c));
    return d;
}
union F4U { float4 f4; unsigned long long u2[2]; };

// ---------------- lift: rho1 -> regular rep ----------------
__global__ void lift_kernel(const float* __restrict__ p0_enc,
                            const float* __restrict__ v0_enc,
                            const float* __restrict__ p0,
                            const float* __restrict__ v0,
                            const float* __restrict__ a,
                            const float* __restrict__ lc,
                            const float* __restrict__ ld) {
    int bi = blockIdx.x;
    int tid = threadIdx.x;
    int c = tid >> 3, m = tid & 7;

    float v0x = v0[bi * 2 + 0], v0y = v0[bi * 2 + 1];
    float ax = a[bi * 2 + 0], ay = a[bi * 2 + 1];
    float v1x = v0x + ax, v1y = v0y + ay;
    float p1x = p0[bi * 2 + 0] + 0.5f * (v0x + v1x);
    float p1y = p0[bi * 2 + 1] + 0.5f * (v0y + v1y);

    float x, y;
    if (c == 0)      { x = v1x; y = v1y; }
    else if (c == 1) { x = p1x; y = p1y; }
    else if (c < 9)  { int t = c - 2; x = v0_enc[(bi * 7 + t) * 2 + 0]; y = v0_enc[(bi * 7 + t) * 2 + 1]; }
    else             { int t = c - 9; x = p0_enc[(bi * 7 + t) * 2 + 0]; y = p0_enc[(bi * 7 + t) * 2 + 1]; }

    float th = (float)m * 0.78539816339744831f;
    float cs = cosf(th), sn = sinf(th);
    float lc0 = lc[0], lc1 = lc[1], ld0 = ld[0], ld1 = ld[1];
    g_regC[bi * 128 + tid] = x * (lc0 * cs - lc1 * sn) + y * (lc0 * sn + lc1 * cs);
    g_regD[bi * 128 + tid] = x * (ld0 * cs - ld1 * sn) + y * (ld0 * sn + ld1 * cs);
}

// ---------------- geometry -> per-particle CSR over 16 t-columns ----------------
__global__ void __launch_bounds__(256) geom_kernel(const float* __restrict__ mask,
                                                   const float* __restrict__ p0,
                                                   const float* __restrict__ v0,
                                                   const float* __restrict__ a) {
    __shared__ float sx[NPART], sy[NPART], smk[NPART], sw[NPART];
    __shared__ float red[256];
    __shared__ int cnt[16], offs[16], bstart[17];
    int bi = blockIdx.x;
    int b = bi >> 9, i = bi & 511;
    int tid = threadIdx.x;

    for (int j = tid; j < NPART; j += 256) {
        int gj = b * NPART + j;
        float vx = v0[gj * 2], vy = v0[gj * 2 + 1];
        sx[j] = p0[gj * 2 + 0] + vx + 0.5f * a[gj * 2 + 0];
        sy[j] = p0[gj * 2 + 1] + vy + 0.5f * a[gj * 2 + 1];
        smk[j] = mask[gj];
    }
    if (tid < 16) cnt[tid] = 0;
    __syncthreads();
    if (tid == 0) { g_p1[bi * 2] = sx[i]; g_p1[bi * 2 + 1] = sy[i]; }
    float xi = sx[i], yi = sy[i];

    float part = 0.f;
    for (int j = tid; j < NPART; j += 256) {
        float rx = sx[j] - xi, ry = sy[j] - yi;
        float d2 = (rx * rx + ry * ry + 1e-12f) * (0.025f * 0.025f);
        float u = fmaxf(1.f - d2, 0.f);
        float w = u * u * u * smk[j];
        sw[j] = w;
        part += w;
    }
    red[tid] = part;
    __syncthreads();
    for (int s = 128; s > 0; s >>= 1) { if (tid < s) red[tid] += red[tid + s]; __syncthreads(); }
    float inv = 1.f / (red[0] + 1e-6f);
    __syncthreads();

    // per-thread locals (2 j's per thread)
    float4 eloc[2];
    int tloc[2];
    int nloc = 0;
#pragma unroll
    for (int c = 0; c < 2; ++c) {
        int j = c * 256 + tid;
        float w = sw[j];
        if (w > 0.f) {
            float rx = sx[j] - xi, ry = sy[j] - yi;
            float d = sqrtf(rx * rx + ry * ry + 1e-12f) * 0.025f;
            float wb = w * inv;
            float rc = fminf(fmaxf(d * 3.f - 0.5f, 0.f), 2.f);
            float r0 = floorf(rc);
            float wr = rc - r0;
            int r0i = (int)r0;
            float axv = (j == i) ? 1.f : rx;
            float ayv = (j == i) ? 0.f : ry;
            float ang = atan2f(ayv, axv);
            ang = ang - TWO_PI * floorf(ang * INV_2PI);
            float tc = ang * (16.f * INV_2PI);
            float t0 = floorf(tc);
            float wt = tc - t0;
            int t0i = ((int)t0) & 15;
            eloc[nloc] = make_float4(wb * (1.f - wr), wb * wr, wt,
                                     __int_as_float(j | (r0i << 16)));
            tloc[nloc] = t0i;
            ++nloc;
            atomicAdd(&cnt[t0i], 1);
        }
    }
    __syncthreads();
    if (tid == 0) {
        int s = 0;
        for (int g = 0; g < 16; ++g) { bstart[g] = s; s += cnt[g]; }
        bstart[16] = s;
    }
    __syncthreads();
    if (tid < 16) offs[tid] = bstart[tid];
    if (tid < 17) g_binStart[bi * 17 + tid] = bstart[tid];
    __syncthreads();

    float4* ent = g_ent + (size_t)bi * 512;
    for (int l = 0; l < nloc; ++l) {
        int pos = atomicAdd(&offs[tloc[l]], 1);
        ent[pos] = eloc[l];
    }
}

// ---------------- expand all weights ----------------
__global__ void expand_all(const float* __restrict__ Wc0, const float* __restrict__ Wc1,
                           const float* __restrict__ Wc2, const float* __restrict__ Wc3,
                           const float* __restrict__ Wc4,
                           const float* __restrict__ Wd0, const float* __restrict__ Wd1,
                           const float* __restrict__ Wd2, const float* __restrict__ Wd3,
                           const float* __restrict__ Wd4) {
    const int Cs[5] = {16, 8, 8, 16, 8};
    const int Os[5] = {4, 8, 16, 8, 3};
    int idx = blockIdx.x * 256 + threadIdx.x;
    if (idx < 1253376) {
        int l = 0;
        while (idx >= c_wOff[l + 1]) ++l;
        int loc = idx - c_wOff[l];
        const float* Wc = (l == 0) ? Wc0 : (l == 1) ? Wc1 : (l == 2) ? Wc2 : (l == 3) ? Wc3 : Wc4;
        int C = Cs[l], OK = Os[l] * 8;
        int om = loc % OK;
        int kk = loc / OK;
        int n = kk & 7;
        int c = (kk >> 3) % C;
        int g = (kk >> 3) / C;
        int r = g >> 4, t = g & 15;
        int o = om >> 3, m = om & 7;
        g_Wbig[idx] = Wc[(((o * C + c) * 8 + ((n - m) & 7)) * 3 + r) * 16 + ((t - 2 * m) & 15)];
    } else if (idx < 1253376 + 26112) {
        int id2 = idx - 1253376;
        int l = 0;
        while (id2 >= c_dOff[l + 1]) ++l;
        int loc = id2 - c_dOff[l];
        const float* Wd = (l == 0) ? Wd0 : (l == 1) ? Wd1 : (l == 2) ? Wd2 : (l == 3) ? Wd3 : Wd4;
        int C = Cs[l], OK = Os[l] * 8;
        int om = loc % OK;
        int cn = loc / OK;
        int o = om >> 3, m = om & 7, c = cn >> 3, n = cn & 7;
        g_WdT[id2] = Wd[(o * C + c) * 8 + ((m - n) & 7)];
    }
}

// ---------------- stage 1: t-column CSR gather ----------------
// warp w owns column t=w (3 radial rows, register accumulators).
// Consumes list t with weight (1-wt) and list (t-1)%16 with weight wt.
template <int CK>
__global__ void __launch_bounds__(512) stage1_kernel(int srcsel) {
    const int VEC = CK / 32;                 // 4 (CK=128) or 2 (CK=64)
    int bi = blockIdx.x;
    int b = bi >> 9;
    int tid = threadIdx.x;
    int warp = tid >> 5, lane = tid & 31;
    const float* __restrict__ feats = (srcsel == 0) ? g_regC : (srcsel == 1) ? g_actA : g_actB;

    __shared__ int bs[17];
    if (tid < 17) bs[tid] = g_binStart[bi * 17 + tid];
    __syncthreads();

    const float4* __restrict__ ent = g_ent + (size_t)bi * 512;
    const float* __restrict__ fb = feats + (size_t)b * NPART * CK;

    float acc0[VEC], acc1[VEC], acc2[VEC];
#pragma unroll
    for (int v = 0; v < VEC; ++v) { acc0[v] = 0.f; acc1[v] = 0.f; acc2[v] = 0.f; }

#pragma unroll
    for (int list = 0; list < 2; ++list) {
        int col = (list == 0) ? warp : ((warp + 15) & 15);
        int s = bs[col], e = bs[col + 1];
        for (int k = s; k < e; ++k) {
            float4 m = ent[k];
            int jr = __float_as_int(m.w);
            int j = jr & 511;
            int r0 = jr >> 16;
            float wtp = (list == 0) ? (1.f - m.z) : m.z;
            float w0 = m.x * wtp, w1 = m.y * wtp;
            float cr0 = 0.f, cr1 = 0.f, cr2 = 0.f;
            if (r0 == 0)      { cr0 = w0; cr1 = w1; }
            else if (r0 == 1) { cr1 = w0; cr2 = w1; }
            else              { cr2 = w0 + w1; }
            if (VEC == 4) {
                float4 f = *(const float4*)(fb + j * CK + lane * 4);
                acc0[0] = fmaf(cr0, f.x, acc0[0]);
                acc0[1] = fmaf(cr0, f.y, acc0[1]);
                acc0[2] = fmaf(cr0, f.z, acc0[2]);
                acc0[3] = fmaf(cr0, f.w, acc0[3]);
                acc1[0] = fmaf(cr1, f.x, acc1[0]);
                acc1[1] = fmaf(cr1, f.y, acc1[1]);
                acc1[2] = fmaf(cr1, f.z, acc1[2]);
                acc1[3] = fmaf(cr1, f.w, acc1[3]);
                acc2[0] = fmaf(cr2, f.x, acc2[0]);
                acc2[1] = fmaf(cr2, f.y, acc2[1]);
                acc2[2] = fmaf(cr2, f.z, acc2[2]);
                acc2[3] = fmaf(cr2, f.w, acc2[3]);
            } else {
                float2 f = *(const float2*)(fb + j * CK + lane * 2);
                acc0[0] = fmaf(cr0, f.x, acc0[0]);
                acc0[1] = fmaf(cr0, f.y, acc0[1]);
                acc1[0] = fmaf(cr1, f.x, acc1[0]);
                acc1[1] = fmaf(cr1, f.y, acc1[1]);
                acc2[0] = fmaf(cr2, f.x, acc2[0]);
                acc2[1] = fmaf(cr2, f.y, acc2[1]);
            }
        }
    }

    float* Fb = g_F + (size_t)bi * GBINS * CK;
    if (VEC == 4) {
        *(float4*)(Fb + (0 * 16 + warp) * CK + lane * 4) = make_float4(acc0[0], acc0[1], acc0[2], acc0[3]);
        *(float4*)(Fb + (1 * 16 + warp) * CK + lane * 4) = make_float4(acc1[0], acc1[1], acc1[2], acc1[3]);
        *(float4*)(Fb + (2 * 16 + warp) * CK + lane * 4) = make_float4(acc2[0], acc2[1], acc2[2], acc2[3]);
    } else {
        *(float2*)(Fb + (0 * 16 + warp) * CK + lane * 2) = make_float2(acc0[0], acc0[1]);
        *(float2*)(Fb + (1 * 16 + warp) * CK + lane * 2) = make_float2(acc1[0], acc1[1]);
        *(float2*)(Fb + (2 * 16 + warp) * CK + lane * 2) = make_float2(acc2[0], acc2[1]);
    }
}

// ---------------- stage 2a: split-K GEMM with f32x2 FMA -> partials ----------------
template <int OK, int TM, int ROWS, int CPT, int KS>
__global__ void __launch_bounds__((TM / ROWS) * (OK / CPT)) gemm_kernel(int KD, int wOff) {
    const int KB = 32;
    const int THREADS = (TM / ROWS) * (OK / CPT);
    const int NW4 = (KB * OK / 4 + THREADS - 1) / THREADS;
    const int NF4 = (TM * KB / 4 + THREADS - 1) / THREADS;
    __shared__ __align__(16) float Wt[KB * OK];
    __shared__ __align__(16) float Ft[TM * KB];
    int tid = threadIdx.x;
    int i0 = blockIdx.x * TM;
    int KC = KD / KS;
    int k0 = blockIdx.y * KC;
    int NCH = KC / KB;

    const float* Wsrc = g_Wbig + wOff + (size_t)k0 * OK;

    float4 wreg[NW4], freg[NF4];
    {
        const float4* src = (const float4*)Wsrc;
#pragma unroll
        for (int u = 0; u < NW4; ++u) {
            int x = tid + u * THREADS;
            if (x < KB * OK / 4) wreg[u] = src[x];
        }
#pragma unroll
        for (int u = 0; u < NF4; ++u) {
            int x = tid + u * THREADS;
            if (x < TM * KB / 4) {
                int row = x / (KB / 4), kc = x % (KB / 4);
                freg[u] = *(const float4*)(g_F + (size_t)(i0 + row) * KD + k0 + kc * 4);
            }
        }
    }

    int rg = tid / (OK / CPT);               // row group (ROWS rows)
    int cg = (tid % (OK / CPT)) * CPT;
    unsigned long long accp[ROWS][CPT / 2];
#pragma unroll
    for (int r = 0; r < ROWS; ++r)
#pragma unroll
        for (int c = 0; c < CPT / 2; ++c) accp[r][c] = 0ull;

    for (int ch = 0; ch < NCH; ++ch) {
        __syncthreads();
#pragma unroll
        for (int u = 0; u < NW4; ++u) {
            int x = tid + u * THREADS;
            if (x < KB * OK / 4) ((float4*)Wt)[x] = wreg[u];
        }
#pragma unroll
        for (int u = 0; u < NF4; ++u) {
            int x = tid + u * THREADS;
            if (x < TM * KB / 4) ((float4*)Ft)[x] = freg[u];
        }
        __syncthreads();
        if (ch + 1 < NCH) {
            const float4* src = (const float4*)(Wsrc + (size_t)(ch + 1) * KB * OK);
#pragma unroll
            for (int u = 0; u < NW4; ++u) {
                int x = tid + u * THREADS;
                if (x < KB * OK / 4) wreg[u] = src[x];
            }
#pragma unroll
            for (int u = 0; u < NF4; ++u) {
                int x = tid + u * THREADS;
                if (x < TM * KB / 4) {
                    int rr = x / (KB / 4), kc = x % (KB / 4);
                    freg[u] = *(const float4*)(g_F + (size_t)(i0 + rr) * KD + k0 + (ch + 1) * KB + kc * 4);
                }
            }
        }
#pragma unroll 4
        for (int k = 0; k < KB; ++k) {
            unsigned long long fp[ROWS];
#pragma unroll
            for (int r = 0; r < ROWS; ++r)
                fp[r] = pack2(Ft[(rg * ROWS + r) * KB + k]);
#pragma unroll
            for (int c = 0; c < CPT; c += 4) {
                F4U w;
                w.f4 = *(const float4*)&Wt[k * OK + cg + c];
#pragma unroll
                for (int r = 0; r < ROWS; ++r) {
                    accp[r][c / 2]     = ffma2(fp[r], w.u2[0], accp[r][c / 2]);
                    accp[r][c / 2 + 1] = ffma2(fp[r], w.u2[1], accp[r][c / 2 + 1]);
                }
            }
        }
    }

#pragma unroll
    for (int r = 0; r < ROWS; ++r) {
        float* dst = g_part + ((size_t)blockIdx.y * BN + i0 + rg * ROWS + r) * OK + cg;
#pragma unroll
        for (int c = 0; c < CPT; c += 4) {
            F4U o;
            o.u2[0] = accp[r][c / 2];
            o.u2[1] = accp[r][c / 2 + 1];
            *(float4*)&dst[c] = o.f4;
        }
    }
}

// ---------------- stage 2b: deterministic reduce + dense + epilogue ----------------
template <int OK, int ROWS>
__global__ void __launch_bounds__(OK * ROWS) reduce_kernel(int KS, int CK, int mode,
                                                           int dOff, int ain, int aout) {
    int tid = threadIdx.x;
    int row = tid / OK, om = tid % OK;
    int bi = blockIdx.x * ROWS + row;

    float oc = 0.f;
    for (int ks = 0; ks < KS; ++ks)
        oc += g_part[((size_t)ks * BN + bi) * OK + om];

    const float* __restrict__ densein = (ain == 0) ? g_regD : (ain == 1) ? g_actA : g_actB;
    float* __restrict__ actout = (aout == 1) ? g_actA : g_actB;
    const float* WdT = g_WdT + dOff;
    const float* x = densein + (size_t)bi * CK;
    float od = 0.f;
    for (int cn = 0; cn < CK; ++cn) od = fmaf(x[cn], WdT[cn * OK + om], od);

    if (mode == 0) {
        g_out[bi * 64 + om] = oc;
        g_out[bi * 64 + 32 + om] = od;
        float sc = oc * oc;
        sc += __shfl_xor_sync(0xffffffffu, sc, 1);
        sc += __shfl_xor_sync(0xffffffffu, sc, 2);
        sc += __shfl_xor_sync(0xffffffffu, sc, 4);
        float mc = sc + 1e-6f;
        actout[bi * 64 + om] = oc / mc * fmaxf(mc - 0.2f, 0.f);
        float sd = od * od;
        sd += __shfl_xor_sync(0xffffffffu, sd, 1);
        sd += __shfl_xor_sync(0xffffffffu, sd, 2);
        sd += __shfl_xor_sync(0xffffffffu, sd, 4);
        float md = sd + 1e-6f;
        actout[bi * 64 + 32 + om] = od / md * fmaxf(md - 0.2f, 0.f);
    } else if (mode == 3) {
        g_oc[bi * 24 + om] = oc;
        g_od[bi * 24 + om] = od;
    } else {
        float v = oc + od;
        if (mode == 2) v += g_out[bi * OK + om];
        g_out[bi * OK + om] = v;
        float sq = v * v;
        sq += __shfl_xor_sync(0xffffffffu, sq, 1);
        sq += __shfl_xor_sync(0xffffffffu, sq, 2);
        sq += __shfl_xor_sync(0xffffffffu, sq, 4);
        float mg = sq + 1e-6f;
        actout[bi * OK + om] = v / mg * fmaxf(mg - 0.2f, 0.f);
    }
}

// ---------------- final projection + correction ----------------
__global__ void final_kernel(const float* __restrict__ p0,
                             const float* __restrict__ pc,
                             const float* __restrict__ pd,
                             float* __restrict__ outp) {
    int bi = blockIdx.x * blockDim.x + threadIdx.x;
    if (bi >= BN) return;
    float res[3][2] = {{0.f, 0.f}, {0.f, 0.f}, {0.f, 0.f}};
    float c0 = pc[0], c1 = pc[1], d0 = pd[0], d1 = pd[1];
#pragma unroll
    for (int m = 0; m < 8; ++m) {
        float th = (float)m * 0.78539816339744831f;
        float cs = cosf(th), sn = sinf(th);
        float Mc0 = c0 * cs - c1 * sn, Mc1 = c0 * sn + c1 * cs;
        float Md0 = d0 * cs - d1 * sn, Md1 = d0 * sn + d1 * cs;
#pragma unroll
        for (int ch = 0; ch < 3; ++ch) {
            float vc = g_oc[bi * 24 + ch * 8 + m];
            float vd = g_od[bi * 24 + ch * 8 + m];
            res[ch][0] += vc * Mc0 + vd * Md0;
            res[ch][1] += vc * Mc1 + vd * Md1;
        }
    }
    const float CORR = 1.0f / 128.0f;
    float pcx = g_p1[bi * 2 + 0] + CORR * res[0][0];
    float pcy = g_p1[bi * 2 + 1] + CORR * res[0][1];
    outp[bi * 2 + 0] = pcx;
    outp[bi * 2 + 1] = pcy;
    outp[BN * 2 + bi * 2 + 0] = pcx - p0[bi * 2 + 0];
    outp[BN * 2 + bi * 2 + 1] = pcy - p0[bi * 2 + 1];
    outp[BN * 4 + bi * 4 + 0] = CORR * res[1][0];
    outp[BN * 4 + bi * 4 + 1] = CORR * res[1][1];
    outp[BN * 4 + bi * 4 + 2] = CORR * res[2][0];
    outp[BN * 4 + bi * 4 + 3] = CORR * res[2][1];
}

// ---------------- launch ----------------
extern "C" void kernel_launch(void* const* d_in, const int* in_sizes, int n_in,
                              void* d_out, int out_size) {
    const float* p0_enc  = (const float*)d_in[0];
    const float* v0_enc  = (const float*)d_in[1];
    const float* p0      = (const float*)d_in[2];
    const float* v0      = (const float*)d_in[3];
    const float* a       = (const float*)d_in[4];
    const float* mask    = (const float*)d_in[5];
    const float* lift_c0 = (const float*)d_in[6];
    const float* Wc0     = (const float*)d_in[7];
    const float* lift_d0 = (const float*)d_in[8];
    const float* Wd0     = (const float*)d_in[9];
    const float* Wc1     = (const float*)d_in[10];
    const float* Wd1     = (const float*)d_in[11];
    const float* Wc2     = (const float*)d_in[12];
    const float* Wd2     = (const float*)d_in[13];
    const float* Wc3     = (const float*)d_in[14];
    const float* Wd3     = (const float*)d_in[15];
    const float* Wc4     = (const float*)d_in[16];
    const float* proj_c4 = (const float*)d_in[17];
    const float* Wd4     = (const float*)d_in[18];
    const float* proj_d4 = (const float*)d_in[19];

    lift_kernel<<<BN, 128>>>(p0_enc, v0_enc, p0, v0, a, lift_c0, lift_d0);
    geom_kernel<<<BN, 256>>>(mask, p0, v0, a);
    expand_all<<<(1253376 + 26112 + 255) / 256, 256>>>(Wc0, Wc1, Wc2, Wc3, Wc4,
                                                       Wd0, Wd1, Wd2, Wd3, Wd4);

    const int wOff[5] = {0, 196608, 393216, 786432, 1179648};
    const int dOff[5] = {0, 4096, 8192, 16384, 24576};

    // act ping-pong: L0 -> A; L1: A->B; L2: B->A; L3: A->B; L4: reads B
    // L0: CK=128, OK=32, KD=6144
    stage1_kernel<128><<<BN, 512>>>(0);
    gemm_kernel<32, 128, 2, 8, 16><<<dim3(8, 16), 256>>>(6144, wOff[0]);
    reduce_kernel<32, 8><<<BN / 8, 256>>>(16, 128, 0, dOff[0], 0, 1);
    // L1: CK=64, OK=64, KD=3072, residual
    stage1_kernel<64><<<BN, 512>>>(1);
    gemm_kernel<64, 64, 2, 8, 8><<<dim3(16, 8), 256>>>(3072, wOff[1]);
    reduce_kernel<64, 4><<<BN / 4, 256>>>(8, 64, 2, dOff[1], 1, 2);
    // L2: CK=64, OK=128, KD=3072
    stage1_kernel<64><<<BN, 512>>>(2);
    gemm_kernel<128, 32, 2, 8, 4><<<dim3(32, 4), 256>>>(3072, wOff[2]);
    reduce_kernel<128, 2><<<BN / 2, 256>>>(4, 64, 1, dOff[2], 2, 1);
    // L3: CK=128, OK=64, KD=6144
    stage1_kernel<128><<<BN, 512>>>(1);
    gemm_kernel<64, 64, 2, 8, 16><<<dim3(16, 16), 256>>>(6144, wOff[3]);
    reduce_kernel<64, 4><<<BN / 4, 256>>>(16, 128, 1, dOff[3], 1, 2);
    // L4: CK=64, OK=24, KD=3072, last
    stage1_kernel<64><<<BN, 512>>>(2);
    gemm_kernel<24, 128, 2, 8, 4><<<dim3(8, 4), 192>>>(3072, wOff[4]);
    reduce_kernel<24, 8><<<BN / 8, 192>>>(4, 64, 3, dOff[4], 2, 2);

    final_kernel<<<4, 256>>>(p0, proj_c4, proj_d4, (float*)d_out);
}